// round 2
// baseline (speedup 1.0000x reference)
#include <cuda_runtime.h>

#define NN 50000
#define NE 500000
#define DN 128
#define DE 64
#define KM 192   // DN + DE   (message GEMM K)
#define KA 256   // 2*DN      (update GEMM K)
#define KE 320   // 2*DN + DE (edge GEMM K)
#define HM 64    // MLP hidden

// ---- scratch (device globals: allocation-free) ----
__device__ float g_x[NN * DN];     // current node features
__device__ float g_ea[NE * DE];    // current edge features
__device__ float g_agg[NN * DN];   // scatter accumulator
__device__ float g_cnt[NN];        // in-degree counts

// ---------------------------------------------------------------------------
__global__ void cnt_kernel(const int* __restrict__ dst) {
    int e = blockIdx.x * blockDim.x + threadIdx.x;
    if (e < NE) atomicAdd(&g_cnt[dst[e]], 1.0f);
}

// ---------------------------------------------------------------------------
// Message: m = relu([x[src], ea] @ Wm + bm); atomicAdd into g_agg[dst].
// TILE = 64 edges / block-iter, 256 threads, each thread: 4 edges x 8 cols.
__global__ void __launch_bounds__(256, 1)
msg_kernel(const float* __restrict__ x, const float* __restrict__ ea,
           const int* __restrict__ src, const int* __restrict__ dst,
           const float* __restrict__ W, const float* __restrict__ b) {
    extern __shared__ float sm[];
    float* Ws  = sm;                   // KM*DN
    float* bs  = Ws + KM * DN;         // DN
    float* ins = bs + DN;              // 64*KM
    int*   ssrc = (int*)(ins + 64 * KM);
    int*   sdst = ssrc + 64;

    const int t = threadIdx.x;
    for (int i = t; i < KM * DN; i += 256) Ws[i] = W[i];
    if (t < DN) bs[t] = b[t];

    const int tx = t & 15;   // cols 8*tx .. 8*tx+7
    const int ty = t >> 4;   // 0..15 -> edges ty*4 .. ty*4+3
    const int ntiles = (NE + 63) >> 6;

    for (int tile = blockIdx.x; tile < ntiles; tile += gridDim.x) {
        __syncthreads();
        if (t < 64) {
            int e = (tile << 6) + t;
            ssrc[t] = (e < NE) ? src[e] : -1;
            sdst[t] = (e < NE) ? dst[e] : -1;
        }
        __syncthreads();
        for (int idx = t; idx < 64 * KM; idx += 256) {
            int it = idx / KM;
            int c  = idx - it * KM;
            int s  = ssrc[it];
            float v = 0.f;
            if (s >= 0) {
                int e = (tile << 6) + it;
                v = (c < DN) ? x[s * DN + c] : ea[e * DE + (c - DN)];
            }
            ins[idx] = v;
        }
        __syncthreads();

        float acc[4][8];
#pragma unroll
        for (int ii = 0; ii < 4; ++ii)
#pragma unroll
            for (int c = 0; c < 8; ++c) acc[ii][c] = 0.f;

        const float* inp = ins + (ty * 4) * KM;
#pragma unroll 2
        for (int k = 0; k < KM; ++k) {
            float4 wa = *(const float4*)(Ws + k * DN + 8 * tx);
            float4 wb = *(const float4*)(Ws + k * DN + 8 * tx + 4);
#pragma unroll
            for (int ii = 0; ii < 4; ++ii) {
                float v = inp[ii * KM + k];
                acc[ii][0] += v * wa.x; acc[ii][1] += v * wa.y;
                acc[ii][2] += v * wa.z; acc[ii][3] += v * wa.w;
                acc[ii][4] += v * wb.x; acc[ii][5] += v * wb.y;
                acc[ii][6] += v * wb.z; acc[ii][7] += v * wb.w;
            }
        }

#pragma unroll
        for (int ii = 0; ii < 4; ++ii) {
            int it = ty * 4 + ii;
            int d  = sdst[it];
            if (d >= 0) {
                float* ag = g_agg + d * DN + 8 * tx;
#pragma unroll
                for (int c = 0; c < 8; ++c) {
                    float m = acc[ii][c] + bs[8 * tx + c];
                    if (m > 0.f) atomicAdd(ag + c, m);  // relu; skip zeros
                }
            }
        }
    }
}

// ---------------------------------------------------------------------------
// Update: x = L2norm(relu([agg/cnt, x] @ Wa + ba)).  TILE=64 nodes, 4x8/thread.
__global__ void __launch_bounds__(256, 1)
upd_kernel(const float* __restrict__ xin,
           const float* __restrict__ W, const float* __restrict__ b) {
    extern __shared__ float sm[];
    float* Ws   = sm;                 // KA*DN
    float* bs   = Ws + KA * DN;       // DN
    float* ins  = bs + DN;            // 64*KA
    float* sinv = ins + 64 * KA;      // 64

    const int t = threadIdx.x;
    for (int i = t; i < KA * DN; i += 256) Ws[i] = W[i];
    if (t < DN) bs[t] = b[t];

    const int tx = t & 15;
    const int ty = t >> 4;
    const int ntiles = (NN + 63) >> 6;

    for (int tile = blockIdx.x; tile < ntiles; tile += gridDim.x) {
        __syncthreads();
        if (t < 64) {
            int i = (tile << 6) + t;
            float c = (i < NN) ? g_cnt[i] : 1.f;
            sinv[t] = 1.f / fmaxf(c, 1.f);
        }
        __syncthreads();
        for (int idx = t; idx < 64 * KA; idx += 256) {
            int it = idx >> 8;        // KA == 256
            int c  = idx & 255;
            int i  = (tile << 6) + it;
            float v = 0.f;
            if (i < NN)
                v = (c < DN) ? g_agg[i * DN + c] * sinv[it]
                             : xin[i * DN + (c - DN)];
            ins[idx] = v;
        }
        __syncthreads();

        float acc[4][8];
#pragma unroll
        for (int ii = 0; ii < 4; ++ii)
#pragma unroll
            for (int c = 0; c < 8; ++c) acc[ii][c] = 0.f;

        const float* inp = ins + (ty * 4) * KA;
#pragma unroll 2
        for (int k = 0; k < KA; ++k) {
            float4 wa = *(const float4*)(Ws + k * DN + 8 * tx);
            float4 wb = *(const float4*)(Ws + k * DN + 8 * tx + 4);
#pragma unroll
            for (int ii = 0; ii < 4; ++ii) {
                float v = inp[ii * KA + k];
                acc[ii][0] += v * wa.x; acc[ii][1] += v * wa.y;
                acc[ii][2] += v * wa.z; acc[ii][3] += v * wa.w;
                acc[ii][4] += v * wb.x; acc[ii][5] += v * wb.y;
                acc[ii][6] += v * wb.z; acc[ii][7] += v * wb.w;
            }
        }

#pragma unroll
        for (int ii = 0; ii < 4; ++ii) {
            int it = ty * 4 + ii;
            int i  = (tile << 6) + it;
            float s = 0.f;
#pragma unroll
            for (int c = 0; c < 8; ++c) {
                float v = fmaxf(acc[ii][c] + bs[8 * tx + c], 0.f);
                acc[ii][c] = v;
                s += v * v;
            }
            // reduce over the 16 lanes (tx group) owning this row
            s += __shfl_xor_sync(0xffffffffu, s, 8);
            s += __shfl_xor_sync(0xffffffffu, s, 4);
            s += __shfl_xor_sync(0xffffffffu, s, 2);
            s += __shfl_xor_sync(0xffffffffu, s, 1);
            float scale = 1.f / fmaxf(sqrtf(s), 1e-12f);
            if (i < NN) {
                float* xo = g_x + i * DN + 8 * tx;
#pragma unroll
                for (int c = 0; c < 8; ++c) xo[c] = acc[ii][c] * scale;
            }
        }
    }
}

// ---------------------------------------------------------------------------
// Edge update: ea = relu([x[src], x[dst], ea] @ We + be).  TILE=64, 4x4/thread.
__global__ void __launch_bounds__(256, 1)
edge_kernel(const float* __restrict__ eain,
            const int* __restrict__ src, const int* __restrict__ dst,
            const float* __restrict__ W, const float* __restrict__ b) {
    extern __shared__ float sm[];
    float* Ws  = sm;                  // KE*DE
    float* bs  = Ws + KE * DE;        // DE
    float* ins = bs + DE;             // 64*KE
    int*   ssrc = (int*)(ins + 64 * KE);
    int*   sdst = ssrc + 64;

    const int t = threadIdx.x;
    for (int i = t; i < KE * DE; i += 256) Ws[i] = W[i];
    if (t < DE) bs[t] = b[t];

    const int tx = t & 15;   // cols 4*tx .. 4*tx+3  (DE=64)
    const int ty = t >> 4;   // 0..15 -> edges ty*4 ..
    const int ntiles = (NE + 63) >> 6;

    for (int tile = blockIdx.x; tile < ntiles; tile += gridDim.x) {
        __syncthreads();
        if (t < 64) {
            int e = (tile << 6) + t;
            ssrc[t] = (e < NE) ? src[e] : -1;
            sdst[t] = (e < NE) ? dst[e] : -1;
        }
        __syncthreads();
        for (int idx = t; idx < 64 * KE; idx += 256) {
            int it = idx / KE;
            int c  = idx - it * KE;
            int s  = ssrc[it];
            float v = 0.f;
            if (s >= 0) {
                int e = (tile << 6) + it;
                v = (c < DN)      ? g_x[s * DN + c]
                  : (c < 2 * DN)  ? g_x[sdst[it] * DN + (c - DN)]
                                  : eain[e * DE + (c - 2 * DN)];
            }
            ins[idx] = v;
        }
        __syncthreads();

        float acc[4][4];
#pragma unroll
        for (int ii = 0; ii < 4; ++ii)
#pragma unroll
            for (int c = 0; c < 4; ++c) acc[ii][c] = 0.f;

        const float* inp = ins + (ty * 4) * KE;
#pragma unroll 2
        for (int k = 0; k < KE; ++k) {
            float4 w = *(const float4*)(Ws + k * DE + 4 * tx);
#pragma unroll
            for (int ii = 0; ii < 4; ++ii) {
                float v = inp[ii * KE + k];
                acc[ii][0] += v * w.x; acc[ii][1] += v * w.y;
                acc[ii][2] += v * w.z; acc[ii][3] += v * w.w;
            }
        }

#pragma unroll
        for (int ii = 0; ii < 4; ++ii) {
            int e = (tile << 6) + ty * 4 + ii;
            if (e < NE) {
                float* eo = g_ea + e * DE + 4 * tx;
#pragma unroll
                for (int c = 0; c < 4; ++c)
                    eo[c] = fmaxf(acc[ii][c] + bs[4 * tx + c], 0.f);
            }
        }
    }
}

// ---------------------------------------------------------------------------
// Head MLP: out = relu(x@W1+b1) @ W2 + b2.  TILE=32 nodes.
__global__ void __launch_bounds__(256, 1)
head_kernel(const float* __restrict__ W1, const float* __restrict__ b1,
            const float* __restrict__ W2, const float* __restrict__ b2,
            float* __restrict__ out) {
    extern __shared__ float sm[];
    float* W1s = sm;                    // DN*HM
    float* b1s = W1s + DN * HM;         // HM
    float* W2s = b1s + HM;              // HM*DN
    float* b2s = W2s + HM * DN;         // DN
    float* ins = b2s + DN;              // 32*DN
    float* hs  = ins + 32 * DN;         // 32*HM

    const int t = threadIdx.x;
    for (int i = t; i < DN * HM; i += 256) W1s[i] = W1[i];
    for (int i = t; i < HM * DN; i += 256) W2s[i] = W2[i];
    if (t < HM) b1s[t] = b1[t];
    if (t < DN) b2s[t] = b2[t];

    const int tx1 = t & 15, ty1 = t >> 4;  // stage1: 2 nodes x 4 cols (HM=64)
    const int tx2 = t & 31, ty2 = t >> 5;  // stage2: 4 nodes x 4 cols (DN=128)
    const int ntiles = (NN + 31) >> 5;

    for (int tile = blockIdx.x; tile < ntiles; tile += gridDim.x) {
        __syncthreads();
        for (int idx = t; idx < 32 * DN; idx += 256) {
            int it = idx >> 7, c = idx & 127;
            int i = (tile << 5) + it;
            ins[idx] = (i < NN) ? g_x[i * DN + c] : 0.f;
        }
        __syncthreads();
        {   // stage 1: h = relu(x @ W1 + b1)
            float acc[2][4] = {{0,0,0,0},{0,0,0,0}};
            const float* inp = ins + (ty1 * 2) * DN;
#pragma unroll 2
            for (int k = 0; k < DN; ++k) {
                float4 w = *(const float4*)(W1s + k * HM + 4 * tx1);
                float v0 = inp[k], v1 = inp[DN + k];
                acc[0][0] += v0 * w.x; acc[0][1] += v0 * w.y;
                acc[0][2] += v0 * w.z; acc[0][3] += v0 * w.w;
                acc[1][0] += v1 * w.x; acc[1][1] += v1 * w.y;
                acc[1][2] += v1 * w.z; acc[1][3] += v1 * w.w;
            }
#pragma unroll
            for (int jj = 0; jj < 2; ++jj) {
                int it = ty1 * 2 + jj;
#pragma unroll
                for (int c = 0; c < 4; ++c)
                    hs[it * HM + 4 * tx1 + c] =
                        fmaxf(acc[jj][c] + b1s[4 * tx1 + c], 0.f);
            }
        }
        __syncthreads();
        {   // stage 2: out = h @ W2 + b2
            float acc[4][4];
#pragma unroll
            for (int ii = 0; ii < 4; ++ii)
#pragma unroll
                for (int c = 0; c < 4; ++c) acc[ii][c] = 0.f;
            const float* inp = hs + (ty2 * 4) * HM;
#pragma unroll 2
            for (int k = 0; k < HM; ++k) {
                float4 w = *(const float4*)(W2s + k * DN + 4 * tx2);
#pragma unroll
                for (int ii = 0; ii < 4; ++ii) {
                    float v = inp[ii * HM + k];
                    acc[ii][0] += v * w.x; acc[ii][1] += v * w.y;
                    acc[ii][2] += v * w.z; acc[ii][3] += v * w.w;
                }
            }
#pragma unroll
            for (int ii = 0; ii < 4; ++ii) {
                int i = (tile << 5) + ty2 * 4 + ii;
                if (i < NN) {
                    float* o = out + i * DN + 4 * tx2;
#pragma unroll
                    for (int c = 0; c < 4; ++c)
                        o[c] = acc[ii][c] + b2s[4 * tx2 + c];
                }
            }
        }
    }
}

// ---------------------------------------------------------------------------
extern "C" void kernel_launch(void* const* d_in, const int* in_sizes, int n_in,
                              void* d_out, int out_size) {
    (void)in_sizes; (void)n_in; (void)out_size;
    const float* x  = (const float*)d_in[0];
    const float* ea = (const float*)d_in[1];
    const int*   ei = (const int*)d_in[2];
    const float* Wm = (const float*)d_in[3];
    const float* bm = (const float*)d_in[4];
    const float* Wa = (const float*)d_in[5];
    const float* ba = (const float*)d_in[6];
    const float* We = (const float*)d_in[7];
    const float* be = (const float*)d_in[8];
    const float* W1 = (const float*)d_in[9];
    const float* b1 = (const float*)d_in[10];
    const float* W2 = (const float*)d_in[11];
    const float* b2 = (const float*)d_in[12];
    float* out = (float*)d_out;
    const int* src = ei;
    const int* dst = ei + NE;

    int nsm = 0;
    cudaDeviceGetAttribute(&nsm, cudaDevAttrMultiProcessorCount, 0);
    if (nsm <= 0) nsm = 148;

    const int SM_MSG = (KM * DN + DN + 64 * KM) * 4 + 64 * 8;
    const int SM_UPD = (KA * DN + DN + 64 * KA + 64) * 4;
    const int SM_EDG = (KE * DE + DE + 64 * KE) * 4 + 64 * 8;
    const int SM_HED = (DN * HM + HM + HM * DN + DN + 32 * DN + 32 * HM) * 4;

    cudaFuncSetAttribute(msg_kernel,  cudaFuncAttributeMaxDynamicSharedMemorySize, SM_MSG);
    cudaFuncSetAttribute(upd_kernel,  cudaFuncAttributeMaxDynamicSharedMemorySize, SM_UPD);
    cudaFuncSetAttribute(edge_kernel, cudaFuncAttributeMaxDynamicSharedMemorySize, SM_EDG);
    cudaFuncSetAttribute(head_kernel, cudaFuncAttributeMaxDynamicSharedMemorySize, SM_HED);

    void *agg_addr = 0, *cnt_addr = 0, *x_addr = 0, *ea_addr = 0;
    cudaGetSymbolAddress(&agg_addr, g_agg);
    cudaGetSymbolAddress(&cnt_addr, g_cnt);
    cudaGetSymbolAddress(&x_addr,  g_x);
    cudaGetSymbolAddress(&ea_addr, g_ea);

    cudaMemsetAsync(cnt_addr, 0, NN * sizeof(float));
    cnt_kernel<<<(NE + 255) / 256, 256>>>(dst);

    for (int l = 0; l < 3; ++l) {
        const float* xl  = (l == 0) ? x  : (const float*)x_addr;
        const float* eal = (l == 0) ? ea : (const float*)ea_addr;
        cudaMemsetAsync(agg_addr, 0, (size_t)NN * DN * sizeof(float));
        msg_kernel<<<nsm, 256, SM_MSG>>>(xl, eal, src, dst,
                                         Wm + l * KM * DN, bm + l * DN);
        upd_kernel<<<nsm, 256, SM_UPD>>>(xl, Wa + l * KA * DN, ba + l * DN);
        edge_kernel<<<nsm, 256, SM_EDG>>>(eal, src, dst,
                                          We + l * KE * DE, be + l * DE);
    }
    head_kernel<<<nsm, 256, SM_HED>>>(W1, b1, W2, b2, out);
}

// round 4
// speedup vs baseline: 3.3454x; 3.3454x over previous
#include <cuda_runtime.h>
#include <cstdint>

#define NN 50000
#define NE 500000
#define DN 128
#define DE 64
#define KA 256
#define HM 64

__device__ float g_x[NN * DN];
__device__ float g_ea[NE * DE];
__device__ float g_agg[NN * DN];
__device__ float g_cnt[NN];

// ===================== helpers =====================
__device__ __forceinline__ uint32_t smem_u32(const void* p) {
    uint32_t a;
    asm("{ .reg .u64 t; cvta.to.shared.u64 t, %1; cvt.u32.u64 %0, t; }" : "=r"(a) : "l"(p));
    return a;
}
#define LDSM4(r0, r1, r2, r3, addr) \
    asm volatile("ldmatrix.sync.aligned.m8n8.x4.shared.b16 {%0,%1,%2,%3}, [%4];" \
                 : "=r"(r0), "=r"(r1), "=r"(r2), "=r"(r3) : "r"(addr))
#define MMA(c, a, b) \
    asm volatile("mma.sync.aligned.m16n8k16.row.col.f32.bf16.bf16.f32 " \
                 "{%0,%1,%2,%3},{%4,%5,%6,%7},{%8,%9},{%0,%1,%2,%3};" \
                 : "+f"((c)[0]), "+f"((c)[1]), "+f"((c)[2]), "+f"((c)[3]) \
                 : "r"((a)[0]), "r"((a)[1]), "r"((a)[2]), "r"((a)[3]), \
                   "r"((b)[0]), "r"((b)[1]))

// hi = truncated-bf16 pair (packed), lo = exact fp32 residual truncated to bf16
__device__ __forceinline__ void splitp(float a, float b, uint32_t& hi, uint32_t& lo) {
    uint32_t ua = __float_as_uint(a), ub = __float_as_uint(b);
    hi = __byte_perm(ua, ub, 0x7632);
    float la = a - __uint_as_float(ua & 0xFFFF0000u);
    float lb = b - __uint_as_float(ub & 0xFFFF0000u);
    lo = __byte_perm(__float_as_uint(la), __float_as_uint(lb), 0x7632);
}

// ===================== cnt =====================
__global__ void cnt_kernel(const int* __restrict__ dst) {
    int e = blockIdx.x * blockDim.x + threadIdx.x;
    if (e < NE) atomicAdd(&g_cnt[dst[e]], 1.0f);
}

// ===================== MESSAGE (mma.sync bf16 3-pass) =====================
// m = relu([x[src], ea] @ Wm + bm) -> atomicAdd g_agg[dst].  K=192, OUT=128.
#define MS_P 400
#define MS_WT_H 0
#define MS_WT_L (128 * MS_P)
#define MS_A_H (2 * 128 * MS_P)
#define MS_A_L (MS_A_H + 64 * MS_P)
#define MS_BIAS (MS_A_L + 64 * MS_P)
#define MS_IDX (MS_BIAS + 512)
#define MS_SMEM (MS_IDX + 512)

__global__ void __launch_bounds__(256, 1)
msg_mma(const float* __restrict__ x, const float* __restrict__ ea,
        const int* __restrict__ src, const int* __restrict__ dst,
        const float* __restrict__ W, const float* __restrict__ bias) {
    extern __shared__ char sm[];
    const uint32_t sb = smem_u32(sm);
    float* bs = (float*)(sm + MS_BIAS);
    int* ssrc = (int*)(sm + MS_IDX);
    int* sdst = ssrc + 64;
    const int t = threadIdx.x, lane = t & 31, wid = t >> 5;

    // stage W^T hi/lo (rows = out channel n, contiguous k), pitch MS_P
    for (int i = t; i < 128 * 96; i += 256) {
        int n = i & 127, kp = i >> 7;
        uint32_t h, l;
        splitp(W[(2 * kp) * DN + n], W[(2 * kp + 1) * DN + n], h, l);
        *(uint32_t*)(sm + MS_WT_H + n * MS_P + kp * 4) = h;
        *(uint32_t*)(sm + MS_WT_L + n * MS_P + kp * 4) = l;
    }
    if (t < 128) bs[t] = bias[t];

    const int we = wid >> 1, wo = wid & 1;           // 4 edge-groups x 2 out-halves
    const int am = we * 16 + (lane & 15);
    const int ak = (lane >> 4) << 3;
    const int bn0 = wo * 64 + (lane & 7) + ((lane >> 4) << 3);
    const int bk = (lane & 8) ? 8 : 0;
    const int ntiles = (NE + 63) >> 6;

    for (int tile = blockIdx.x; tile < ntiles; tile += gridDim.x) {
        __syncthreads();
        if (t < 64) {
            int e = tile * 64 + t;
            ssrc[t] = (e < NE) ? src[e] : -1;
            sdst[t] = (e < NE) ? dst[e] : -1;
        }
        __syncthreads();
        for (int i = t; i < 64 * 24; i += 256) {
            int row = i / 24, g = i - row * 24, k0 = g * 8;
            int s = ssrc[row];
            uint4 H = make_uint4(0, 0, 0, 0), L = H;
            if (s >= 0) {
                const float* p = (k0 < DN) ? x + (size_t)s * DN + k0
                                           : ea + (size_t)(tile * 64 + row) * DE + (k0 - DN);
                float4 v0 = *(const float4*)p, v1 = *(const float4*)(p + 4);
                splitp(v0.x, v0.y, H.x, L.x); splitp(v0.z, v0.w, H.y, L.y);
                splitp(v1.x, v1.y, H.z, L.z); splitp(v1.z, v1.w, H.w, L.w);
            }
            *(uint4*)(sm + MS_A_H + row * MS_P + g * 16) = H;
            *(uint4*)(sm + MS_A_L + row * MS_P + g * 16) = L;
        }
        __syncthreads();

        float c[8][4];
#pragma unroll
        for (int n = 0; n < 8; ++n) { c[n][0] = c[n][1] = c[n][2] = c[n][3] = 0.f; }
#pragma unroll
        for (int ks = 0; ks < 12; ++ks) {
            int k0 = ks * 16;
            uint32_t ah[4], al[4];
            uint32_t aoff = am * MS_P + (k0 + ak) * 2;
            LDSM4(ah[0], ah[1], ah[2], ah[3], sb + MS_A_H + aoff);
            LDSM4(al[0], al[1], al[2], al[3], sb + MS_A_L + aoff);
            uint32_t Bh[8][2], Bl[8][2];
#pragma unroll
            for (int p = 0; p < 4; ++p) {
                uint32_t boff = (uint32_t)(bn0 + p * 16) * MS_P + (k0 + bk) * 2;
                LDSM4(Bh[2 * p][0], Bh[2 * p][1], Bh[2 * p + 1][0], Bh[2 * p + 1][1],
                      sb + MS_WT_H + boff);
                LDSM4(Bl[2 * p][0], Bl[2 * p][1], Bl[2 * p + 1][0], Bl[2 * p + 1][1],
                      sb + MS_WT_L + boff);
            }
#pragma unroll
            for (int n = 0; n < 8; ++n) MMA(c[n], ah, Bh[n]);
#pragma unroll
            for (int n = 0; n < 8; ++n) MMA(c[n], ah, Bl[n]);
#pragma unroll
            for (int n = 0; n < 8; ++n) MMA(c[n], al, Bh[n]);
        }
        int r0 = we * 16 + (lane >> 2), r1 = r0 + 8;
        int d0 = sdst[r0], d1 = sdst[r1];
#pragma unroll
        for (int n = 0; n < 8; ++n) {
            int col = wo * 64 + n * 8 + (lane & 3) * 2;
            float b0 = bs[col], b1 = bs[col + 1];
            float v;
            if (d0 >= 0) {
                v = c[n][0] + b0; if (v > 0.f) atomicAdd(g_agg + (size_t)d0 * DN + col, v);
                v = c[n][1] + b1; if (v > 0.f) atomicAdd(g_agg + (size_t)d0 * DN + col + 1, v);
            }
            if (d1 >= 0) {
                v = c[n][2] + b0; if (v > 0.f) atomicAdd(g_agg + (size_t)d1 * DN + col, v);
                v = c[n][3] + b1; if (v > 0.f) atomicAdd(g_agg + (size_t)d1 * DN + col + 1, v);
            }
        }
    }
}

// ===================== EDGE (mma.sync bf16 3-pass) =====================
// ea = relu([x[src], x[dst], ea] @ We + be).  K=320, OUT=64.
#define ED_P 656
#define ED_WT_H 0
#define ED_WT_L (64 * ED_P)
#define ED_A_H (2 * 64 * ED_P)
#define ED_A_L (ED_A_H + 64 * ED_P)
#define ED_BIAS (ED_A_L + 64 * ED_P)
#define ED_IDX (ED_BIAS + 256)
#define ED_SMEM (ED_IDX + 512)

__global__ void __launch_bounds__(256, 1)
edge_mma(const float* __restrict__ eain,
         const int* __restrict__ src, const int* __restrict__ dst,
         const float* __restrict__ W, const float* __restrict__ bias) {
    extern __shared__ char sm[];
    const uint32_t sb = smem_u32(sm);
    float* bs = (float*)(sm + ED_BIAS);
    int* ssrc = (int*)(sm + ED_IDX);
    int* sdst = ssrc + 64;
    const int t = threadIdx.x, lane = t & 31, wid = t >> 5;

    for (int i = t; i < 64 * 160; i += 256) {
        int n = i & 63, kp = i >> 6;
        uint32_t h, l;
        splitp(W[(2 * kp) * DE + n], W[(2 * kp + 1) * DE + n], h, l);
        *(uint32_t*)(sm + ED_WT_H + n * ED_P + kp * 4) = h;
        *(uint32_t*)(sm + ED_WT_L + n * ED_P + kp * 4) = l;
    }
    if (t < 64) bs[t] = bias[t];

    const int we = wid >> 1, wo = wid & 1;
    const int am = we * 16 + (lane & 15);
    const int ak = (lane >> 4) << 3;
    const int bn0 = wo * 32 + (lane & 7) + ((lane >> 4) << 3);
    const int bk = (lane & 8) ? 8 : 0;
    const int ntiles = (NE + 63) >> 6;

    for (int tile = blockIdx.x; tile < ntiles; tile += gridDim.x) {
        __syncthreads();
        if (t < 64) {
            int e = tile * 64 + t;
            ssrc[t] = (e < NE) ? src[e] : -1;
            sdst[t] = (e < NE) ? dst[e] : -1;
        }
        __syncthreads();
        for (int i = t; i < 64 * 40; i += 256) {
            int row = i / 40, g = i - row * 40, k0 = g * 8;
            int s = ssrc[row];
            uint4 H = make_uint4(0, 0, 0, 0), L = H;
            if (s >= 0) {
                const float* p;
                if (k0 < DN)          p = g_x + (size_t)s * DN + k0;
                else if (k0 < 2 * DN) p = g_x + (size_t)sdst[row] * DN + (k0 - DN);
                else                  p = eain + (size_t)(tile * 64 + row) * DE + (k0 - 2 * DN);
                float4 v0 = *(const float4*)p, v1 = *(const float4*)(p + 4);
                splitp(v0.x, v0.y, H.x, L.x); splitp(v0.z, v0.w, H.y, L.y);
                splitp(v1.x, v1.y, H.z, L.z); splitp(v1.z, v1.w, H.w, L.w);
            }
            *(uint4*)(sm + ED_A_H + row * ED_P + g * 16) = H;
            *(uint4*)(sm + ED_A_L + row * ED_P + g * 16) = L;
        }
        __syncthreads();

        float c[4][4];
#pragma unroll
        for (int n = 0; n < 4; ++n) { c[n][0] = c[n][1] = c[n][2] = c[n][3] = 0.f; }
#pragma unroll
        for (int ks = 0; ks < 20; ++ks) {
            int k0 = ks * 16;
            uint32_t ah[4], al[4];
            uint32_t aoff = am * ED_P + (k0 + ak) * 2;
            LDSM4(ah[0], ah[1], ah[2], ah[3], sb + ED_A_H + aoff);
            LDSM4(al[0], al[1], al[2], al[3], sb + ED_A_L + aoff);
            uint32_t Bh[4][2], Bl[4][2];
#pragma unroll
            for (int p = 0; p < 2; ++p) {
                uint32_t boff = (uint32_t)(bn0 + p * 16) * ED_P + (k0 + bk) * 2;
                LDSM4(Bh[2 * p][0], Bh[2 * p][1], Bh[2 * p + 1][0], Bh[2 * p + 1][1],
                      sb + ED_WT_H + boff);
                LDSM4(Bl[2 * p][0], Bl[2 * p][1], Bl[2 * p + 1][0], Bl[2 * p + 1][1],
                      sb + ED_WT_L + boff);
            }
#pragma unroll
            for (int n = 0; n < 4; ++n) MMA(c[n], ah, Bh[n]);
#pragma unroll
            for (int n = 0; n < 4; ++n) MMA(c[n], ah, Bl[n]);
#pragma unroll
            for (int n = 0; n < 4; ++n) MMA(c[n], al, Bh[n]);
        }
        int r0 = we * 16 + (lane >> 2), r1 = r0 + 8;
        int e0 = tile * 64 + r0, e1 = tile * 64 + r1;
#pragma unroll
        for (int n = 0; n < 4; ++n) {
            int col = wo * 32 + n * 8 + (lane & 3) * 2;
            float b0 = bs[col], b1 = bs[col + 1];
            if (e0 < NE) {
                float2 v = make_float2(fmaxf(c[n][0] + b0, 0.f), fmaxf(c[n][1] + b1, 0.f));
                *(float2*)(g_ea + (size_t)e0 * DE + col) = v;
            }
            if (e1 < NE) {
                float2 v = make_float2(fmaxf(c[n][2] + b0, 0.f), fmaxf(c[n][3] + b1, 0.f));
                *(float2*)(g_ea + (size_t)e1 * DE + col) = v;
            }
        }
    }
}

// ===================== UPDATE (SIMT, validated) =====================
__global__ void __launch_bounds__(256, 1)
upd_kernel(const float* __restrict__ xin,
           const float* __restrict__ W, const float* __restrict__ b) {
    extern __shared__ float smf[];
    float* Ws = smf;
    float* bs = Ws + KA * DN;
    float* ins = bs + DN;
    float* sinv = ins + 64 * KA;
    const int t = threadIdx.x;
    for (int i = t; i < KA * DN; i += 256) Ws[i] = W[i];
    if (t < DN) bs[t] = b[t];
    const int tx = t & 15, ty = t >> 4;
    const int ntiles = (NN + 63) >> 6;
    for (int tile = blockIdx.x; tile < ntiles; tile += gridDim.x) {
        __syncthreads();
        if (t < 64) {
            int i = (tile << 6) + t;
            float c = (i < NN) ? g_cnt[i] : 1.f;
            sinv[t] = 1.f / fmaxf(c, 1.f);
        }
        __syncthreads();
        for (int idx = t; idx < 64 * KA; idx += 256) {
            int it = idx >> 8, c = idx & 255;
            int i = (tile << 6) + it;
            float v = 0.f;
            if (i < NN)
                v = (c < DN) ? g_agg[(size_t)i * DN + c] * sinv[it]
                             : xin[(size_t)i * DN + (c - DN)];
            ins[idx] = v;
        }
        __syncthreads();
        float acc[4][8];
#pragma unroll
        for (int ii = 0; ii < 4; ++ii)
#pragma unroll
            for (int c = 0; c < 8; ++c) acc[ii][c] = 0.f;
        const float* inp = ins + (ty * 4) * KA;
#pragma unroll 2
        for (int k = 0; k < KA; ++k) {
            float4 wa = *(const float4*)(Ws + k * DN + 8 * tx);
            float4 wb = *(const float4*)(Ws + k * DN + 8 * tx + 4);
#pragma unroll
            for (int ii = 0; ii < 4; ++ii) {
                float v = inp[ii * KA + k];
                acc[ii][0] += v * wa.x; acc[ii][1] += v * wa.y;
                acc[ii][2] += v * wa.z; acc[ii][3] += v * wa.w;
                acc[ii][4] += v * wb.x; acc[ii][5] += v * wb.y;
                acc[ii][6] += v * wb.z; acc[ii][7] += v * wb.w;
            }
        }
#pragma unroll
        for (int ii = 0; ii < 4; ++ii) {
            int i = (tile << 6) + ty * 4 + ii;
            float s = 0.f;
#pragma unroll
            for (int c = 0; c < 8; ++c) {
                float v = fmaxf(acc[ii][c] + bs[8 * tx + c], 0.f);
                acc[ii][c] = v;
                s += v * v;
            }
            s += __shfl_xor_sync(0xffffffffu, s, 8);
            s += __shfl_xor_sync(0xffffffffu, s, 4);
            s += __shfl_xor_sync(0xffffffffu, s, 2);
            s += __shfl_xor_sync(0xffffffffu, s, 1);
            float scale = 1.f / fmaxf(sqrtf(s), 1e-12f);
            if (i < NN) {
                float* xo = g_x + (size_t)i * DN + 8 * tx;
#pragma unroll
                for (int c = 0; c < 8; ++c) xo[c] = acc[ii][c] * scale;
            }
        }
    }
}

// ===================== HEAD (SIMT, validated) =====================
__global__ void __launch_bounds__(256, 1)
head_kernel(const float* __restrict__ W1, const float* __restrict__ b1,
            const float* __restrict__ W2, const float* __restrict__ b2,
            float* __restrict__ out) {
    extern __shared__ float smf[];
    float* W1s = smf;
    float* b1s = W1s + DN * HM;
    float* W2s = b1s + HM;
    float* b2s = W2s + HM * DN;
    float* ins = b2s + DN;
    float* hs = ins + 32 * DN;
    const int t = threadIdx.x;
    for (int i = t; i < DN * HM; i += 256) W1s[i] = W1[i];
    for (int i = t; i < HM * DN; i += 256) W2s[i] = W2[i];
    if (t < HM) b1s[t] = b1[t];
    if (t < DN) b2s[t] = b2[t];
    const int tx1 = t & 15, ty1 = t >> 4;
    const int tx2 = t & 31, ty2 = t >> 5;
    const int ntiles = (NN + 31) >> 5;
    for (int tile = blockIdx.x; tile < ntiles; tile += gridDim.x) {
        __syncthreads();
        for (int idx = t; idx < 32 * DN; idx += 256) {
            int it = idx >> 7, c = idx & 127;
            int i = (tile << 5) + it;
            ins[idx] = (i < NN) ? g_x[(size_t)i * DN + c] : 0.f;
        }
        __syncthreads();
        {
            float acc[2][4] = {{0, 0, 0, 0}, {0, 0, 0, 0}};
            const float* inp = ins + (ty1 * 2) * DN;
#pragma unroll 2
            for (int k = 0; k < DN; ++k) {
                float4 w = *(const float4*)(W1s + k * HM + 4 * tx1);
                float v0 = inp[k], v1 = inp[DN + k];
                acc[0][0] += v0 * w.x; acc[0][1] += v0 * w.y;
                acc[0][2] += v0 * w.z; acc[0][3] += v0 * w.w;
                acc[1][0] += v1 * w.x; acc[1][1] += v1 * w.y;
                acc[1][2] += v1 * w.z; acc[1][3] += v1 * w.w;
            }
#pragma unroll
            for (int jj = 0; jj < 2; ++jj) {
                int it = ty1 * 2 + jj;
#pragma unroll
                for (int c = 0; c < 4; ++c)
                    hs[it * HM + 4 * tx1 + c] = fmaxf(acc[jj][c] + b1s[4 * tx1 + c], 0.f);
            }
        }
        __syncthreads();
        {
            float acc[4][4];
#pragma unroll
            for (int ii = 0; ii < 4; ++ii)
#pragma unroll
                for (int c = 0; c < 4; ++c) acc[ii][c] = 0.f;
            const float* inp = hs + (ty2 * 4) * HM;
#pragma unroll 2
            for (int k = 0; k < HM; ++k) {
                float4 w = *(const float4*)(W2s + k * DN + 4 * tx2);
#pragma unroll
                for (int ii = 0; ii < 4; ++ii) {
                    float v = inp[ii * HM + k];
                    acc[ii][0] += v * w.x; acc[ii][1] += v * w.y;
                    acc[ii][2] += v * w.z; acc[ii][3] += v * w.w;
                }
            }
#pragma unroll
            for (int ii = 0; ii < 4; ++ii) {
                int i = (tile << 5) + ty2 * 4 + ii;
                if (i < NN) {
                    float* o = out + (size_t)i * DN + 4 * tx2;
#pragma unroll
                    for (int c = 0; c < 4; ++c) o[c] = acc[ii][c] + b2s[4 * tx2 + c];
                }
            }
        }
    }
}

// ===================== launch =====================
extern "C" void kernel_launch(void* const* d_in, const int* in_sizes, int n_in,
                              void* d_out, int out_size) {
    (void)in_sizes; (void)n_in; (void)out_size;
    const float* x  = (const float*)d_in[0];
    const float* ea = (const float*)d_in[1];
    const int*   ei = (const int*)d_in[2];
    const float* Wm = (const float*)d_in[3];
    const float* bm = (const float*)d_in[4];
    const float* Wa = (const float*)d_in[5];
    const float* ba = (const float*)d_in[6];
    const float* We = (const float*)d_in[7];
    const float* be = (const float*)d_in[8];
    const float* W1 = (const float*)d_in[9];
    const float* b1 = (const float*)d_in[10];
    const float* W2 = (const float*)d_in[11];
    const float* b2 = (const float*)d_in[12];
    float* out = (float*)d_out;
    const int* src = ei;
    const int* dst = ei + NE;

    int nsm = 0;
    cudaDeviceGetAttribute(&nsm, cudaDevAttrMultiProcessorCount, 0);
    if (nsm <= 0) nsm = 148;

    const int SM_UPD = (KA * DN + DN + 64 * KA + 64) * 4;
    const int SM_HED = (DN * HM + HM + HM * DN + DN + 32 * DN + 32 * HM) * 4;

    cudaFuncSetAttribute(msg_mma,  cudaFuncAttributeMaxDynamicSharedMemorySize, MS_SMEM);
    cudaFuncSetAttribute(edge_mma, cudaFuncAttributeMaxDynamicSharedMemorySize, ED_SMEM);
    cudaFuncSetAttribute(upd_kernel,  cudaFuncAttributeMaxDynamicSharedMemorySize, SM_UPD);
    cudaFuncSetAttribute(head_kernel, cudaFuncAttributeMaxDynamicSharedMemorySize, SM_HED);

    void *agg_addr = 0, *cnt_addr = 0;
    cudaGetSymbolAddress(&agg_addr, g_agg);
    cudaGetSymbolAddress(&cnt_addr, g_cnt);
    void *x_addr = 0, *ea_addr = 0;
    cudaGetSymbolAddress(&x_addr, g_x);
    cudaGetSymbolAddress(&ea_addr, g_ea);

    cudaMemsetAsync(cnt_addr, 0, NN * sizeof(float));
    cnt_kernel<<<(NE + 255) / 256, 256>>>(dst);

    for (int l = 0; l < 3; ++l) {
        const float* xl  = (l == 0) ? x  : (const float*)x_addr;
        const float* eal = (l == 0) ? ea : (const float*)ea_addr;
        cudaMemsetAsync(agg_addr, 0, (size_t)NN * DN * sizeof(float));
        msg_mma<<<nsm, 256, MS_SMEM>>>(xl, eal, src, dst,
                                       Wm + (size_t)l * (DN + DE) * DN, bm + l * DN);
        upd_kernel<<<nsm, 256, SM_UPD>>>(xl, Wa + (size_t)l * KA * DN, ba + l * DN);
        edge_mma<<<nsm, 256, ED_SMEM>>>(eal, src, dst,
                                        We + (size_t)l * (2 * DN + DE) * DE, be + l * DE);
    }
    head_kernel<<<nsm, 256, SM_HED>>>(W1, b1, W2, b2, out);
}

// round 5
// speedup vs baseline: 3.9350x; 1.1762x over previous
#include <cuda_runtime.h>
#include <cstdint>

#define NN 50000
#define NE 500000
#define DN 128
#define DE 64
#define KA 256
#define HM 64

__device__ float g_x[NN * DN];
__device__ float g_ea[NE * DE];
__device__ float g_agg[NN * DN];
__device__ float g_cnt[NN];

// ===================== helpers =====================
__device__ __forceinline__ uint32_t smem_u32(const void* p) {
    uint32_t a;
    asm("{ .reg .u64 t; cvta.to.shared.u64 t, %1; cvt.u32.u64 %0, t; }" : "=r"(a) : "l"(p));
    return a;
}
#define LDSM4(r0, r1, r2, r3, addr) \
    asm volatile("ldmatrix.sync.aligned.m8n8.x4.shared.b16 {%0,%1,%2,%3}, [%4];" \
                 : "=r"(r0), "=r"(r1), "=r"(r2), "=r"(r3) : "r"(addr))
#define MMA(c, a, b) \
    asm volatile("mma.sync.aligned.m16n8k16.row.col.f32.bf16.bf16.f32 " \
                 "{%0,%1,%2,%3},{%4,%5,%6,%7},{%8,%9},{%0,%1,%2,%3};" \
                 : "+f"((c)[0]), "+f"((c)[1]), "+f"((c)[2]), "+f"((c)[3]) \
                 : "r"((a)[0]), "r"((a)[1]), "r"((a)[2]), "r"((a)[3]), \
                   "r"((b)[0]), "r"((b)[1]))

__device__ __forceinline__ void splitp(float a, float b, uint32_t& hi, uint32_t& lo) {
    uint32_t ua = __float_as_uint(a), ub = __float_as_uint(b);
    hi = __byte_perm(ua, ub, 0x7632);
    float la = a - __uint_as_float(ua & 0xFFFF0000u);
    float lb = b - __uint_as_float(ub & 0xFFFF0000u);
    lo = __byte_perm(__float_as_uint(la), __float_as_uint(lb), 0x7632);
}

// ===================== cnt =====================
__global__ void cnt_kernel(const int* __restrict__ dst) {
    int e = blockIdx.x * blockDim.x + threadIdx.x;
    if (e < NE) atomicAdd(&g_cnt[dst[e]], 1.0f);
}

// ===================== MESSAGE (mma, 512 thr, 128-edge tile) ==============
#define MS_P 400
#define MS_WT_H 0
#define MS_WT_L (128 * MS_P)
#define MS_A_H (2 * 128 * MS_P)
#define MS_A_L (3 * 128 * MS_P)
#define MS_BIAS (4 * 128 * MS_P)
#define MS_IDX (MS_BIAS + 512)
#define MS_SMEM (MS_IDX + 1024)

__global__ void __launch_bounds__(512, 1)
msg_mma(const float* __restrict__ x, const float* __restrict__ ea,
        const int* __restrict__ src, const int* __restrict__ dst,
        const float* __restrict__ W, const float* __restrict__ bias) {
    extern __shared__ char sm[];
    const uint32_t sb = smem_u32(sm);
    float* bs = (float*)(sm + MS_BIAS);
    int* ssrc = (int*)(sm + MS_IDX);
    int* sdst = ssrc + 128;
    const int t = threadIdx.x, lane = t & 31, wid = t >> 5;

    for (int i = t; i < 128 * 96; i += 512) {
        int n = i & 127, kp = i >> 7;
        uint32_t h, l;
        splitp(W[(2 * kp) * DN + n], W[(2 * kp + 1) * DN + n], h, l);
        *(uint32_t*)(sm + MS_WT_H + n * MS_P + kp * 4) = h;
        *(uint32_t*)(sm + MS_WT_L + n * MS_P + kp * 4) = l;
    }
    if (t < 128) bs[t] = bias[t];

    const int we = wid >> 1, wo = wid & 1;         // 8 edge-groups x 2 out-halves
    const int am = we * 16 + (lane & 15);
    const int ak = (lane >> 4) << 3;
    const int bn0 = wo * 64 + (lane & 7) + ((lane >> 4) << 3);
    const int bk = (lane & 8) ? 8 : 0;
    const int ntiles = (NE + 127) >> 7;

    for (int tile = blockIdx.x; tile < ntiles; tile += gridDim.x) {
        __syncthreads();
        if (t < 128) {
            int e = tile * 128 + t;
            ssrc[t] = (e < NE) ? src[e] : -1;
            sdst[t] = (e < NE) ? dst[e] : -1;
        }
        __syncthreads();
        for (int i = t; i < 128 * 24; i += 512) {
            int row = i / 24, g = i - row * 24, k0 = g * 8;
            int s = ssrc[row];
            uint4 H = make_uint4(0, 0, 0, 0), L = H;
            if (s >= 0) {
                const float* p = (k0 < DN) ? x + (size_t)s * DN + k0
                                           : ea + (size_t)(tile * 128 + row) * DE + (k0 - DN);
                float4 v0 = *(const float4*)p, v1 = *(const float4*)(p + 4);
                splitp(v0.x, v0.y, H.x, L.x); splitp(v0.z, v0.w, H.y, L.y);
                splitp(v1.x, v1.y, H.z, L.z); splitp(v1.z, v1.w, H.w, L.w);
            }
            *(uint4*)(sm + MS_A_H + row * MS_P + g * 16) = H;
            *(uint4*)(sm + MS_A_L + row * MS_P + g * 16) = L;
        }
        __syncthreads();

        float c[8][4];
#pragma unroll
        for (int n = 0; n < 8; ++n) { c[n][0] = c[n][1] = c[n][2] = c[n][3] = 0.f; }
#pragma unroll
        for (int ks = 0; ks < 12; ++ks) {
            int k0 = ks * 16;
            uint32_t ah[4], al[4];
            uint32_t aoff = am * MS_P + (k0 + ak) * 2;
            LDSM4(ah[0], ah[1], ah[2], ah[3], sb + MS_A_H + aoff);
            LDSM4(al[0], al[1], al[2], al[3], sb + MS_A_L + aoff);
            uint32_t Bh[8][2], Bl[8][2];
#pragma unroll
            for (int p = 0; p < 4; ++p) {
                uint32_t boff = (uint32_t)(bn0 + p * 16) * MS_P + (k0 + bk) * 2;
                LDSM4(Bh[2 * p][0], Bh[2 * p][1], Bh[2 * p + 1][0], Bh[2 * p + 1][1],
                      sb + MS_WT_H + boff);
                LDSM4(Bl[2 * p][0], Bl[2 * p][1], Bl[2 * p + 1][0], Bl[2 * p + 1][1],
                      sb + MS_WT_L + boff);
            }
#pragma unroll
            for (int n = 0; n < 8; ++n) MMA(c[n], ah, Bh[n]);
#pragma unroll
            for (int n = 0; n < 8; ++n) MMA(c[n], ah, Bl[n]);
#pragma unroll
            for (int n = 0; n < 8; ++n) MMA(c[n], al, Bh[n]);
        }
        int r0 = we * 16 + (lane >> 2), r1 = r0 + 8;
        int d0 = sdst[r0], d1 = sdst[r1];
#pragma unroll
        for (int n = 0; n < 8; ++n) {
            int col = wo * 64 + n * 8 + (lane & 3) * 2;
            float b0 = bs[col], b1 = bs[col + 1];
            float v;
            if (d0 >= 0) {
                v = c[n][0] + b0; if (v > 0.f) atomicAdd(g_agg + (size_t)d0 * DN + col, v);
                v = c[n][1] + b1; if (v > 0.f) atomicAdd(g_agg + (size_t)d0 * DN + col + 1, v);
            }
            if (d1 >= 0) {
                v = c[n][2] + b0; if (v > 0.f) atomicAdd(g_agg + (size_t)d1 * DN + col, v);
                v = c[n][3] + b1; if (v > 0.f) atomicAdd(g_agg + (size_t)d1 * DN + col + 1, v);
            }
        }
    }
}

// ===================== EDGE (mma, 512 thr, split-K) ========================
// 16 warps = 4 edge-groups x 2 col-halves x 2 K-halves (160 each).
#define ED_P 656
#define ED_WT_H 0
#define ED_WT_L (64 * ED_P)
#define ED_A_H (2 * 64 * ED_P)
#define ED_A_L (3 * 64 * ED_P)
#define ED_PART (4 * 64 * ED_P)
#define ED_BIAS (ED_PART + 64 * 64 * 4)
#define ED_IDX (ED_BIAS + 256)
#define ED_SMEM (ED_IDX + 1024)

__global__ void __launch_bounds__(512, 1)
edge_mma(const float* __restrict__ eain,
         const int* __restrict__ src, const int* __restrict__ dst,
         const float* __restrict__ W, const float* __restrict__ bias) {
    extern __shared__ char sm[];
    const uint32_t sb = smem_u32(sm);
    float* bs = (float*)(sm + ED_BIAS);
    float* P = (float*)(sm + ED_PART);
    int* ssrc = (int*)(sm + ED_IDX);
    int* sdst = ssrc + 64;
    const int t = threadIdx.x, lane = t & 31, wid = t >> 5;

    for (int i = t; i < 64 * 160; i += 512) {
        int n = i & 63, kp = i >> 6;
        uint32_t h, l;
        splitp(W[(2 * kp) * DE + n], W[(2 * kp + 1) * DE + n], h, l);
        *(uint32_t*)(sm + ED_WT_H + n * ED_P + kp * 4) = h;
        *(uint32_t*)(sm + ED_WT_L + n * ED_P + kp * 4) = l;
    }
    if (t < 64) bs[t] = bias[t];

    const int wk = wid >> 3;             // K-half
    const int w8 = wid & 7;
    const int we = w8 >> 1, wo = w8 & 1;
    const int am = we * 16 + (lane & 15);
    const int ak = (lane >> 4) << 3;
    const int bn0 = wo * 32 + (lane & 7) + ((lane >> 4) << 3);
    const int bk = (lane & 8) ? 8 : 0;
    const int ntiles = (NE + 63) >> 6;

    for (int tile = blockIdx.x; tile < ntiles; tile += gridDim.x) {
        __syncthreads();
        if (t < 64) {
            int e = tile * 64 + t;
            ssrc[t] = (e < NE) ? src[e] : -1;
            sdst[t] = (e < NE) ? dst[e] : -1;
        }
        __syncthreads();
        for (int i = t; i < 64 * 40; i += 512) {
            int row = i / 40, g = i - row * 40, k0 = g * 8;
            int s = ssrc[row];
            uint4 H = make_uint4(0, 0, 0, 0), L = H;
            if (s >= 0) {
                const float* p;
                if (k0 < DN)          p = g_x + (size_t)s * DN + k0;
                else if (k0 < 2 * DN) p = g_x + (size_t)sdst[row] * DN + (k0 - DN);
                else                  p = eain + (size_t)(tile * 64 + row) * DE + (k0 - 2 * DN);
                float4 v0 = *(const float4*)p, v1 = *(const float4*)(p + 4);
                splitp(v0.x, v0.y, H.x, L.x); splitp(v0.z, v0.w, H.y, L.y);
                splitp(v1.x, v1.y, H.z, L.z); splitp(v1.z, v1.w, H.w, L.w);
            }
            *(uint4*)(sm + ED_A_H + row * ED_P + g * 16) = H;
            *(uint4*)(sm + ED_A_L + row * ED_P + g * 16) = L;
        }
        __syncthreads();

        float c[4][4];
#pragma unroll
        for (int n = 0; n < 4; ++n) { c[n][0] = c[n][1] = c[n][2] = c[n][3] = 0.f; }
#pragma unroll
        for (int j = 0; j < 10; ++j) {
            int k0 = (wk * 10 + j) * 16;
            uint32_t ah[4], al[4];
            uint32_t aoff = am * ED_P + (k0 + ak) * 2;
            LDSM4(ah[0], ah[1], ah[2], ah[3], sb + ED_A_H + aoff);
            LDSM4(al[0], al[1], al[2], al[3], sb + ED_A_L + aoff);
            uint32_t Bh[4][2], Bl[4][2];
#pragma unroll
            for (int p = 0; p < 2; ++p) {
                uint32_t boff = (uint32_t)(bn0 + p * 16) * ED_P + (k0 + bk) * 2;
                LDSM4(Bh[2 * p][0], Bh[2 * p][1], Bh[2 * p + 1][0], Bh[2 * p + 1][1],
                      sb + ED_WT_H + boff);
                LDSM4(Bl[2 * p][0], Bl[2 * p][1], Bl[2 * p + 1][0], Bl[2 * p + 1][1],
                      sb + ED_WT_L + boff);
            }
#pragma unroll
            for (int n = 0; n < 4; ++n) MMA(c[n], ah, Bh[n]);
#pragma unroll
            for (int n = 0; n < 4; ++n) MMA(c[n], ah, Bl[n]);
#pragma unroll
            for (int n = 0; n < 4; ++n) MMA(c[n], al, Bh[n]);
        }
        int r0 = we * 16 + (lane >> 2), r1 = r0 + 8;
        if (wk == 0) {  // write partials
#pragma unroll
            for (int n = 0; n < 4; ++n) {
                int col = wo * 32 + n * 8 + (lane & 3) * 2;
                *(float2*)(P + r0 * 64 + col) = make_float2(c[n][0], c[n][1]);
                *(float2*)(P + r1 * 64 + col) = make_float2(c[n][2], c[n][3]);
            }
        }
        __syncthreads();
        if (wk == 1) {  // combine + epilogue
            int e0 = tile * 64 + r0, e1 = tile * 64 + r1;
#pragma unroll
            for (int n = 0; n < 4; ++n) {
                int col = wo * 32 + n * 8 + (lane & 3) * 2;
                float b0 = bs[col], b1 = bs[col + 1];
                float2 p0 = *(float2*)(P + r0 * 64 + col);
                float2 p1 = *(float2*)(P + r1 * 64 + col);
                if (e0 < NE) {
                    float2 v = make_float2(fmaxf(c[n][0] + p0.x + b0, 0.f),
                                           fmaxf(c[n][1] + p0.y + b1, 0.f));
                    *(float2*)(g_ea + (size_t)e0 * DE + col) = v;
                }
                if (e1 < NE) {
                    float2 v = make_float2(fmaxf(c[n][2] + p1.x + b0, 0.f),
                                           fmaxf(c[n][3] + p1.y + b1, 0.f));
                    *(float2*)(g_ea + (size_t)e1 * DE + col) = v;
                }
            }
        }
    }
}

// ===================== UPDATE (SIMT, 512 thr) =====================
__global__ void __launch_bounds__(512, 1)
upd_kernel(const float* __restrict__ xin,
           const float* __restrict__ W, const float* __restrict__ b) {
    extern __shared__ float smf[];
    float* Ws = smf;
    float* bs = Ws + KA * DN;
    float* ins = bs + DN;
    float* sinv = ins + 64 * KA;
    const int t = threadIdx.x;
    for (int i = t; i < KA * DN; i += 512) Ws[i] = W[i];
    if (t < DN) bs[t] = b[t];
    const int tx = t & 15, ty = t >> 4;   // ty 0..31 -> 2 nodes each
    const int ntiles = (NN + 63) >> 6;
    for (int tile = blockIdx.x; tile < ntiles; tile += gridDim.x) {
        __syncthreads();
        if (t < 64) {
            int i = (tile << 6) + t;
            float c = (i < NN) ? g_cnt[i] : 1.f;
            sinv[t] = 1.f / fmaxf(c, 1.f);
        }
        __syncthreads();
        for (int idx = t; idx < 64 * KA; idx += 512) {
            int it = idx >> 8, c = idx & 255;
            int i = (tile << 6) + it;
            float v = 0.f;
            if (i < NN)
                v = (c < DN) ? g_agg[(size_t)i * DN + c] * sinv[it]
                             : xin[(size_t)i * DN + (c - DN)];
            ins[idx] = v;
        }
        __syncthreads();
        float acc[2][8];
#pragma unroll
        for (int ii = 0; ii < 2; ++ii)
#pragma unroll
            for (int c = 0; c < 8; ++c) acc[ii][c] = 0.f;
        const float* inp = ins + (ty * 2) * KA;
#pragma unroll 2
        for (int k = 0; k < KA; ++k) {
            float4 wa = *(const float4*)(Ws + k * DN + 8 * tx);
            float4 wb = *(const float4*)(Ws + k * DN + 8 * tx + 4);
#pragma unroll
            for (int ii = 0; ii < 2; ++ii) {
                float v = inp[ii * KA + k];
                acc[ii][0] += v * wa.x; acc[ii][1] += v * wa.y;
                acc[ii][2] += v * wa.z; acc[ii][3] += v * wa.w;
                acc[ii][4] += v * wb.x; acc[ii][5] += v * wb.y;
                acc[ii][6] += v * wb.z; acc[ii][7] += v * wb.w;
            }
        }
#pragma unroll
        for (int ii = 0; ii < 2; ++ii) {
            int i = (tile << 6) + ty * 2 + ii;
            float s = 0.f;
#pragma unroll
            for (int c = 0; c < 8; ++c) {
                float v = fmaxf(acc[ii][c] + bs[8 * tx + c], 0.f);
                acc[ii][c] = v;
                s += v * v;
            }
            s += __shfl_xor_sync(0xffffffffu, s, 8);
            s += __shfl_xor_sync(0xffffffffu, s, 4);
            s += __shfl_xor_sync(0xffffffffu, s, 2);
            s += __shfl_xor_sync(0xffffffffu, s, 1);
            float scale = 1.f / fmaxf(sqrtf(s), 1e-12f);
            if (i < NN) {
                float* xo = g_x + (size_t)i * DN + 8 * tx;
#pragma unroll
                for (int c = 0; c < 8; ++c) xo[c] = acc[ii][c] * scale;
            }
        }
    }
}

// ===================== HEAD (SIMT, validated) =====================
__global__ void __launch_bounds__(256, 1)
head_kernel(const float* __restrict__ W1, const float* __restrict__ b1,
            const float* __restrict__ W2, const float* __restrict__ b2,
            float* __restrict__ out) {
    extern __shared__ float smf[];
    float* W1s = smf;
    float* b1s = W1s + DN * HM;
    float* W2s = b1s + HM;
    float* b2s = W2s + HM * DN;
    float* ins = b2s + DN;
    float* hs = ins + 32 * DN;
    const int t = threadIdx.x;
    for (int i = t; i < DN * HM; i += 256) W1s[i] = W1[i];
    for (int i = t; i < HM * DN; i += 256) W2s[i] = W2[i];
    if (t < HM) b1s[t] = b1[t];
    if (t < DN) b2s[t] = b2[t];
    const int tx1 = t & 15, ty1 = t >> 4;
    const int tx2 = t & 31, ty2 = t >> 5;
    const int ntiles = (NN + 31) >> 5;
    for (int tile = blockIdx.x; tile < ntiles; tile += gridDim.x) {
        __syncthreads();
        for (int idx = t; idx < 32 * DN; idx += 256) {
            int it = idx >> 7, c = idx & 127;
            int i = (tile << 5) + it;
            ins[idx] = (i < NN) ? g_x[(size_t)i * DN + c] : 0.f;
        }
        __syncthreads();
        {
            float acc[2][4] = {{0, 0, 0, 0}, {0, 0, 0, 0}};
            const float* inp = ins + (ty1 * 2) * DN;
#pragma unroll 2
            for (int k = 0; k < DN; ++k) {
                float4 w = *(const float4*)(W1s + k * HM + 4 * tx1);
                float v0 = inp[k], v1 = inp[DN + k];
                acc[0][0] += v0 * w.x; acc[0][1] += v0 * w.y;
                acc[0][2] += v0 * w.z; acc[0][3] += v0 * w.w;
                acc[1][0] += v1 * w.x; acc[1][1] += v1 * w.y;
                acc[1][2] += v1 * w.z; acc[1][3] += v1 * w.w;
            }
#pragma unroll
            for (int jj = 0; jj < 2; ++jj) {
                int it = ty1 * 2 + jj;
#pragma unroll
                for (int c = 0; c < 4; ++c)
                    hs[it * HM + 4 * tx1 + c] = fmaxf(acc[jj][c] + b1s[4 * tx1 + c], 0.f);
            }
        }
        __syncthreads();
        {
            float acc[4][4];
#pragma unroll
            for (int ii = 0; ii < 4; ++ii)
#pragma unroll
                for (int c = 0; c < 4; ++c) acc[ii][c] = 0.f;
            const float* inp = hs + (ty2 * 4) * HM;
#pragma unroll 2
            for (int k = 0; k < HM; ++k) {
                float4 w = *(const float4*)(W2s + k * DN + 4 * tx2);
#pragma unroll
                for (int ii = 0; ii < 4; ++ii) {
                    float v = inp[ii * HM + k];
                    acc[ii][0] += v * w.x; acc[ii][1] += v * w.y;
                    acc[ii][2] += v * w.z; acc[ii][3] += v * w.w;
                }
            }
#pragma unroll
            for (int ii = 0; ii < 4; ++ii) {
                int i = (tile << 5) + ty2 * 4 + ii;
                if (i < NN) {
                    float* o = out + (size_t)i * DN + 4 * tx2;
#pragma unroll
                    for (int c = 0; c < 4; ++c) o[c] = acc[ii][c] + b2s[4 * tx2 + c];
                }
            }
        }
    }
}

// ===================== launch =====================
extern "C" void kernel_launch(void* const* d_in, const int* in_sizes, int n_in,
                              void* d_out, int out_size) {
    (void)in_sizes; (void)n_in; (void)out_size;
    const float* x  = (const float*)d_in[0];
    const float* ea = (const float*)d_in[1];
    const int*   ei = (const int*)d_in[2];
    const float* Wm = (const float*)d_in[3];
    const float* bm = (const float*)d_in[4];
    const float* Wa = (const float*)d_in[5];
    const float* ba = (const float*)d_in[6];
    const float* We = (const float*)d_in[7];
    const float* be = (const float*)d_in[8];
    const float* W1 = (const float*)d_in[9];
    const float* b1 = (const float*)d_in[10];
    const float* W2 = (const float*)d_in[11];
    const float* b2 = (const float*)d_in[12];
    float* out = (float*)d_out;
    const int* src = ei;
    const int* dst = ei + NE;

    int nsm = 0;
    cudaDeviceGetAttribute(&nsm, cudaDevAttrMultiProcessorCount, 0);
    if (nsm <= 0) nsm = 148;

    const int SM_UPD = (KA * DN + DN + 64 * KA + 64) * 4;
    const int SM_HED = (DN * HM + HM + HM * DN + DN + 32 * DN + 32 * HM) * 4;

    cudaFuncSetAttribute(msg_mma,  cudaFuncAttributeMaxDynamicSharedMemorySize, MS_SMEM);
    cudaFuncSetAttribute(edge_mma, cudaFuncAttributeMaxDynamicSharedMemorySize, ED_SMEM);
    cudaFuncSetAttribute(upd_kernel,  cudaFuncAttributeMaxDynamicSharedMemorySize, SM_UPD);
    cudaFuncSetAttribute(head_kernel, cudaFuncAttributeMaxDynamicSharedMemorySize, SM_HED);

    void *agg_addr = 0, *cnt_addr = 0, *x_addr = 0, *ea_addr = 0;
    cudaGetSymbolAddress(&agg_addr, g_agg);
    cudaGetSymbolAddress(&cnt_addr, g_cnt);
    cudaGetSymbolAddress(&x_addr, g_x);
    cudaGetSymbolAddress(&ea_addr, g_ea);

    cudaMemsetAsync(cnt_addr, 0, NN * sizeof(float));
    cnt_kernel<<<(NE + 255) / 256, 256>>>(dst);

    for (int l = 0; l < 3; ++l) {
        const float* xl  = (l == 0) ? x  : (const float*)x_addr;
        const float* eal = (l == 0) ? ea : (const float*)ea_addr;
        cudaMemsetAsync(agg_addr, 0, (size_t)NN * DN * sizeof(float));
        msg_mma<<<nsm, 512, MS_SMEM>>>(xl, eal, src, dst,
                                       Wm + (size_t)l * (DN + DE) * DN, bm + l * DN);
        upd_kernel<<<nsm, 512, SM_UPD>>>(xl, Wa + (size_t)l * KA * DN, ba + l * DN);
        edge_mma<<<nsm, 512, ED_SMEM>>>(eal, src, dst,
                                        We + (size_t)l * (2 * DN + DE) * DE, be + l * DE);
    }
    head_kernel<<<nsm, 256, SM_HED>>>(W1, b1, W2, b2, out);
}

// round 6
// speedup vs baseline: 4.1326x; 1.0502x over previous
#include <cuda_runtime.h>
#include <cstdint>

#define NN 50000
#define NE 500000
#define DN 128
#define DE 64
#define KA 256
#define HM 64

__device__ float g_x[NN * DN];
__device__ float g_ea[NE * DE];
__device__ float g_agg[NN * DN];
__device__ float g_cnt[NN];

// ===================== helpers =====================
__device__ __forceinline__ uint32_t smem_u32(const void* p) {
    uint32_t a;
    asm("{ .reg .u64 t; cvta.to.shared.u64 t, %1; cvt.u32.u64 %0, t; }" : "=r"(a) : "l"(p));
    return a;
}
#define LDSM4(r0, r1, r2, r3, addr) \
    asm volatile("ldmatrix.sync.aligned.m8n8.x4.shared.b16 {%0,%1,%2,%3}, [%4];" \
                 : "=r"(r0), "=r"(r1), "=r"(r2), "=r"(r3) : "r"(addr))
#define MMA(c, a, b) \
    asm volatile("mma.sync.aligned.m16n8k16.row.col.f32.bf16.bf16.f32 " \
                 "{%0,%1,%2,%3},{%4,%5,%6,%7},{%8,%9},{%0,%1,%2,%3};" \
                 : "+f"((c)[0]), "+f"((c)[1]), "+f"((c)[2]), "+f"((c)[3]) \
                 : "r"((a)[0]), "r"((a)[1]), "r"((a)[2]), "r"((a)[3]), \
                   "r"((b)[0]), "r"((b)[1]))
#define BARG(id) asm volatile("bar.sync %0, %1;" :: "r"(id), "r"(256) : "memory")

__device__ __forceinline__ void splitp(float a, float b, uint32_t& hi, uint32_t& lo) {
    uint32_t ua = __float_as_uint(a), ub = __float_as_uint(b);
    hi = __byte_perm(ua, ub, 0x7632);
    float la = a - __uint_as_float(ua & 0xFFFF0000u);
    float lb = b - __uint_as_float(ub & 0xFFFF0000u);
    lo = __byte_perm(__float_as_uint(la), __float_as_uint(lb), 0x7632);
}

// ===================== cnt =====================
__global__ void cnt_kernel(const int* __restrict__ dst) {
    int e = blockIdx.x * blockDim.x + threadIdx.x;
    if (e < NE) atomicAdd(&g_cnt[dst[e]], 1.0f);
}

// ============ MESSAGE: 2 ping-pong groups x 64-edge subtiles ============
#define MS_P 400
#define MS_WT_H 0
#define MS_WT_L 51200
#define MS_AB 102400          // + g*51200 : A_H ; +25600 : A_L
#define MS_BIAS 204800
#define MS_IDX 205312         // + g*512
#define MS_SMEM 206336

__global__ void __launch_bounds__(512, 1)
msg_mma(const float* __restrict__ x, const float* __restrict__ ea,
        const int* __restrict__ src, const int* __restrict__ dst,
        const float* __restrict__ W, const float* __restrict__ bias) {
    extern __shared__ char sm[];
    const uint32_t sb = smem_u32(sm);
    float* bs = (float*)(sm + MS_BIAS);
    const int t = threadIdx.x, lane = t & 31, wid = t >> 5;
    const int g = wid >> 3, w8 = wid & 7, t8 = t & 255;

    for (int i = t; i < 128 * 96; i += 512) {
        int n = i & 127, kp = i >> 7;
        uint32_t h, l;
        splitp(W[(2 * kp) * DN + n], W[(2 * kp + 1) * DN + n], h, l);
        *(uint32_t*)(sm + MS_WT_H + n * MS_P + kp * 4) = h;
        *(uint32_t*)(sm + MS_WT_L + n * MS_P + kp * 4) = l;
    }
    if (t < 128) bs[t] = bias[t];
    __syncthreads();

    const int AH = MS_AB + g * 51200, AL = AH + 25600;
    int* ssrc = (int*)(sm + MS_IDX + g * 512);
    int* sdst = ssrc + 64;
    const int bar = 1 + g;

    const int we = w8 >> 1, wo = w8 & 1;
    const int am = we * 16 + (lane & 15);
    const int ak = (lane >> 4) << 3;
    const int bn0 = wo * 64 + (lane & 7) + ((lane >> 4) << 3);
    const int bk = (lane & 8) ? 8 : 0;
    const int ntiles = (NE + 63) >> 6;

    for (int tile = blockIdx.x * 2 + g; tile < ntiles; tile += gridDim.x * 2) {
        BARG(bar);
        if (t8 < 64) {
            int e = tile * 64 + t8;
            ssrc[t8] = (e < NE) ? src[e] : -1;
            sdst[t8] = (e < NE) ? dst[e] : -1;
        }
        BARG(bar);
        for (int i = t8; i < 64 * 24; i += 256) {
            int row = i / 24, gg = i - row * 24, k0 = gg * 8;
            int s = ssrc[row];
            uint4 H = make_uint4(0, 0, 0, 0), L = H;
            if (s >= 0) {
                const float* p = (k0 < DN) ? x + (size_t)s * DN + k0
                                           : ea + (size_t)(tile * 64 + row) * DE + (k0 - DN);
                float4 v0 = *(const float4*)p, v1 = *(const float4*)(p + 4);
                splitp(v0.x, v0.y, H.x, L.x); splitp(v0.z, v0.w, H.y, L.y);
                splitp(v1.x, v1.y, H.z, L.z); splitp(v1.z, v1.w, H.w, L.w);
            }
            *(uint4*)(sm + AH + row * MS_P + gg * 16) = H;
            *(uint4*)(sm + AL + row * MS_P + gg * 16) = L;
        }
        BARG(bar);

        float c[8][4];
#pragma unroll
        for (int n = 0; n < 8; ++n) { c[n][0] = c[n][1] = c[n][2] = c[n][3] = 0.f; }
#pragma unroll
        for (int ks = 0; ks < 12; ++ks) {
            int k0 = ks * 16;
            uint32_t ah[4], al[4];
            uint32_t aoff = am * MS_P + (k0 + ak) * 2;
            LDSM4(ah[0], ah[1], ah[2], ah[3], sb + AH + aoff);
            LDSM4(al[0], al[1], al[2], al[3], sb + AL + aoff);
            uint32_t Bh[8][2], Bl[8][2];
#pragma unroll
            for (int p = 0; p < 4; ++p) {
                uint32_t boff = (uint32_t)(bn0 + p * 16) * MS_P + (k0 + bk) * 2;
                LDSM4(Bh[2 * p][0], Bh[2 * p][1], Bh[2 * p + 1][0], Bh[2 * p + 1][1],
                      sb + MS_WT_H + boff);
                LDSM4(Bl[2 * p][0], Bl[2 * p][1], Bl[2 * p + 1][0], Bl[2 * p + 1][1],
                      sb + MS_WT_L + boff);
            }
#pragma unroll
            for (int n = 0; n < 8; ++n) MMA(c[n], ah, Bh[n]);
#pragma unroll
            for (int n = 0; n < 8; ++n) MMA(c[n], ah, Bl[n]);
#pragma unroll
            for (int n = 0; n < 8; ++n) MMA(c[n], al, Bh[n]);
        }
        int r0 = we * 16 + (lane >> 2), r1 = r0 + 8;
        int d0 = sdst[r0], d1 = sdst[r1];
#pragma unroll
        for (int n = 0; n < 8; ++n) {
            int col = wo * 64 + n * 8 + (lane & 3) * 2;
            float b0 = bs[col], b1 = bs[col + 1];
            float v;
            if (d0 >= 0) {
                v = c[n][0] + b0; if (v > 0.f) atomicAdd(g_agg + (size_t)d0 * DN + col, v);
                v = c[n][1] + b1; if (v > 0.f) atomicAdd(g_agg + (size_t)d0 * DN + col + 1, v);
            }
            if (d1 >= 0) {
                v = c[n][2] + b0; if (v > 0.f) atomicAdd(g_agg + (size_t)d1 * DN + col, v);
                v = c[n][3] + b1; if (v > 0.f) atomicAdd(g_agg + (size_t)d1 * DN + col + 1, v);
            }
        }
    }
}

// ============ EDGE: 2 ping-pong groups x 32-edge subtiles, split-K ============
#define ED_P 656
#define ED_WT_H 0
#define ED_WT_L 41984
#define ED_GRP 83968          // + g*50176 : A_H ; +20992 : A_L ; +41984 : P
#define ED_BIAS 184320
#define ED_IDX 184576         // + g*256
#define ED_SMEM 185088

__global__ void __launch_bounds__(512, 1)
edge_mma(const float* __restrict__ eain,
         const int* __restrict__ src, const int* __restrict__ dst,
         const float* __restrict__ W, const float* __restrict__ bias) {
    extern __shared__ char sm[];
    const uint32_t sb = smem_u32(sm);
    float* bs = (float*)(sm + ED_BIAS);
    const int t = threadIdx.x, lane = t & 31, wid = t >> 5;
    const int g = wid >> 3, w8 = wid & 7, t8 = t & 255;

    for (int i = t; i < 64 * 160; i += 512) {
        int n = i & 63, kp = i >> 6;
        uint32_t h, l;
        splitp(W[(2 * kp) * DE + n], W[(2 * kp + 1) * DE + n], h, l);
        *(uint32_t*)(sm + ED_WT_H + n * ED_P + kp * 4) = h;
        *(uint32_t*)(sm + ED_WT_L + n * ED_P + kp * 4) = l;
    }
    if (t < 64) bs[t] = bias[t];
    __syncthreads();

    const int AH = ED_GRP + g * 50176, AL = AH + 20992;
    float* P = (float*)(sm + AH + 41984);
    int* ssrc = (int*)(sm + ED_IDX + g * 256);
    int* sdst = ssrc + 32;
    const int bar = 1 + g;

    const int wk = w8 >> 2;                // K-half (160 each)
    const int rr = (w8 >> 1) & 1, wo = w8 & 1;
    const int am = rr * 16 + (lane & 15);
    const int ak = (lane >> 4) << 3;
    const int bn0 = wo * 32 + (lane & 7) + ((lane >> 4) << 3);
    const int bk = (lane & 8) ? 8 : 0;
    const int ntiles = (NE + 31) >> 5;

    for (int tile = blockIdx.x * 2 + g; tile < ntiles; tile += gridDim.x * 2) {
        BARG(bar);
        if (t8 < 32) {
            int e = tile * 32 + t8;
            ssrc[t8] = (e < NE) ? src[e] : -1;
            sdst[t8] = (e < NE) ? dst[e] : -1;
        }
        BARG(bar);
        for (int i = t8; i < 32 * 40; i += 256) {
            int row = i / 40, gg = i - row * 40, k0 = gg * 8;
            int s = ssrc[row];
            uint4 H = make_uint4(0, 0, 0, 0), L = H;
            if (s >= 0) {
                const float* p;
                if (k0 < DN)          p = g_x + (size_t)s * DN + k0;
                else if (k0 < 2 * DN) p = g_x + (size_t)sdst[row] * DN + (k0 - DN);
                else                  p = eain + (size_t)(tile * 32 + row) * DE + (k0 - 2 * DN);
                float4 v0 = *(const float4*)p, v1 = *(const float4*)(p + 4);
                splitp(v0.x, v0.y, H.x, L.x); splitp(v0.z, v0.w, H.y, L.y);
                splitp(v1.x, v1.y, H.z, L.z); splitp(v1.z, v1.w, H.w, L.w);
            }
            *(uint4*)(sm + AH + row * ED_P + gg * 16) = H;
            *(uint4*)(sm + AL + row * ED_P + gg * 16) = L;
        }
        BARG(bar);

        float c[4][4];
#pragma unroll
        for (int n = 0; n < 4; ++n) { c[n][0] = c[n][1] = c[n][2] = c[n][3] = 0.f; }
#pragma unroll
        for (int j = 0; j < 10; ++j) {
            int k0 = (wk * 10 + j) * 16;
            uint32_t ah[4], al[4];
            uint32_t aoff = am * ED_P + (k0 + ak) * 2;
            LDSM4(ah[0], ah[1], ah[2], ah[3], sb + AH + aoff);
            LDSM4(al[0], al[1], al[2], al[3], sb + AL + aoff);
            uint32_t Bh[4][2], Bl[4][2];
#pragma unroll
            for (int p = 0; p < 2; ++p) {
                uint32_t boff = (uint32_t)(bn0 + p * 16) * ED_P + (k0 + bk) * 2;
                LDSM4(Bh[2 * p][0], Bh[2 * p][1], Bh[2 * p + 1][0], Bh[2 * p + 1][1],
                      sb + ED_WT_H + boff);
                LDSM4(Bl[2 * p][0], Bl[2 * p][1], Bl[2 * p + 1][0], Bl[2 * p + 1][1],
                      sb + ED_WT_L + boff);
            }
#pragma unroll
            for (int n = 0; n < 4; ++n) MMA(c[n], ah, Bh[n]);
#pragma unroll
            for (int n = 0; n < 4; ++n) MMA(c[n], ah, Bl[n]);
#pragma unroll
            for (int n = 0; n < 4; ++n) MMA(c[n], al, Bh[n]);
        }
        int r0 = rr * 16 + (lane >> 2), r1 = r0 + 8;
        if (wk == 0) {
#pragma unroll
            for (int n = 0; n < 4; ++n) {
                int col = wo * 32 + n * 8 + (lane & 3) * 2;
                *(float2*)(P + r0 * 64 + col) = make_float2(c[n][0], c[n][1]);
                *(float2*)(P + r1 * 64 + col) = make_float2(c[n][2], c[n][3]);
            }
        }
        BARG(bar);
        if (wk == 1) {
            int e0 = tile * 32 + r0, e1 = tile * 32 + r1;
#pragma unroll
            for (int n = 0; n < 4; ++n) {
                int col = wo * 32 + n * 8 + (lane & 3) * 2;
                float b0 = bs[col], b1 = bs[col + 1];
                float2 p0 = *(float2*)(P + r0 * 64 + col);
                float2 p1 = *(float2*)(P + r1 * 64 + col);
                if (e0 < NE) {
                    float2 v = make_float2(fmaxf(c[n][0] + p0.x + b0, 0.f),
                                           fmaxf(c[n][1] + p0.y + b1, 0.f));
                    *(float2*)(g_ea + (size_t)e0 * DE + col) = v;
                }
                if (e1 < NE) {
                    float2 v = make_float2(fmaxf(c[n][2] + p1.x + b0, 0.f),
                                           fmaxf(c[n][3] + p1.y + b1, 0.f));
                    *(float2*)(g_ea + (size_t)e1 * DE + col) = v;
                }
            }
        }
    }
}

// ===================== UPDATE (SIMT, 512 thr) =====================
__global__ void __launch_bounds__(512, 1)
upd_kernel(const float* __restrict__ xin,
           const float* __restrict__ W, const float* __restrict__ b) {
    extern __shared__ float smf[];
    float* Ws = smf;
    float* bs = Ws + KA * DN;
    float* ins = bs + DN;
    float* sinv = ins + 64 * KA;
    const int t = threadIdx.x;
    for (int i = t; i < KA * DN; i += 512) Ws[i] = W[i];
    if (t < DN) bs[t] = b[t];
    const int tx = t & 15, ty = t >> 4;
    const int ntiles = (NN + 63) >> 6;
    for (int tile = blockIdx.x; tile < ntiles; tile += gridDim.x) {
        __syncthreads();
        if (t < 64) {
            int i = (tile << 6) + t;
            float c = (i < NN) ? g_cnt[i] : 1.f;
            sinv[t] = 1.f / fmaxf(c, 1.f);
        }
        __syncthreads();
        for (int idx = t; idx < 64 * KA; idx += 512) {
            int it = idx >> 8, c = idx & 255;
            int i = (tile << 6) + it;
            float v = 0.f;
            if (i < NN)
                v = (c < DN) ? g_agg[(size_t)i * DN + c] * sinv[it]
                             : xin[(size_t)i * DN + (c - DN)];
            ins[idx] = v;
        }
        __syncthreads();
        float acc[2][8];
#pragma unroll
        for (int ii = 0; ii < 2; ++ii)
#pragma unroll
            for (int c = 0; c < 8; ++c) acc[ii][c] = 0.f;
        const float* inp = ins + (ty * 2) * KA;
#pragma unroll 2
        for (int k = 0; k < KA; ++k) {
            float4 wa = *(const float4*)(Ws + k * DN + 8 * tx);
            float4 wb = *(const float4*)(Ws + k * DN + 8 * tx + 4);
#pragma unroll
            for (int ii = 0; ii < 2; ++ii) {
                float v = inp[ii * KA + k];
                acc[ii][0] += v * wa.x; acc[ii][1] += v * wa.y;
                acc[ii][2] += v * wa.z; acc[ii][3] += v * wa.w;
                acc[ii][4] += v * wb.x; acc[ii][5] += v * wb.y;
                acc[ii][6] += v * wb.z; acc[ii][7] += v * wb.w;
            }
        }
#pragma unroll
        for (int ii = 0; ii < 2; ++ii) {
            int i = (tile << 6) + ty * 2 + ii;
            float s = 0.f;
#pragma unroll
            for (int c = 0; c < 8; ++c) {
                float v = fmaxf(acc[ii][c] + bs[8 * tx + c], 0.f);
                acc[ii][c] = v;
                s += v * v;
            }
            s += __shfl_xor_sync(0xffffffffu, s, 8);
            s += __shfl_xor_sync(0xffffffffu, s, 4);
            s += __shfl_xor_sync(0xffffffffu, s, 2);
            s += __shfl_xor_sync(0xffffffffu, s, 1);
            float scale = 1.f / fmaxf(sqrtf(s), 1e-12f);
            if (i < NN) {
                float* xo = g_x + (size_t)i * DN + 8 * tx;
#pragma unroll
                for (int c = 0; c < 8; ++c) xo[c] = acc[ii][c] * scale;
            }
        }
    }
}

// ===================== HEAD (SIMT) =====================
__global__ void __launch_bounds__(256, 1)
head_kernel(const float* __restrict__ W1, const float* __restrict__ b1,
            const float* __restrict__ W2, const float* __restrict__ b2,
            float* __restrict__ out) {
    extern __shared__ float smf[];
    float* W1s = smf;
    float* b1s = W1s + DN * HM;
    float* W2s = b1s + HM;
    float* b2s = W2s + HM * DN;
    float* ins = b2s + DN;
    float* hs = ins + 32 * DN;
    const int t = threadIdx.x;
    for (int i = t; i < DN * HM; i += 256) W1s[i] = W1[i];
    for (int i = t; i < HM * DN; i += 256) W2s[i] = W2[i];
    if (t < HM) b1s[t] = b1[t];
    if (t < DN) b2s[t] = b2[t];
    const int tx1 = t & 15, ty1 = t >> 4;
    const int tx2 = t & 31, ty2 = t >> 5;
    const int ntiles = (NN + 31) >> 5;
    for (int tile = blockIdx.x; tile < ntiles; tile += gridDim.x) {
        __syncthreads();
        for (int idx = t; idx < 32 * DN; idx += 256) {
            int it = idx >> 7, c = idx & 127;
            int i = (tile << 5) + it;
            ins[idx] = (i < NN) ? g_x[(size_t)i * DN + c] : 0.f;
        }
        __syncthreads();
        {
            float acc[2][4] = {{0, 0, 0, 0}, {0, 0, 0, 0}};
            const float* inp = ins + (ty1 * 2) * DN;
#pragma unroll 2
            for (int k = 0; k < DN; ++k) {
                float4 w = *(const float4*)(W1s + k * HM + 4 * tx1);
                float v0 = inp[k], v1 = inp[DN + k];
                acc[0][0] += v0 * w.x; acc[0][1] += v0 * w.y;
                acc[0][2] += v0 * w.z; acc[0][3] += v0 * w.w;
                acc[1][0] += v1 * w.x; acc[1][1] += v1 * w.y;
                acc[1][2] += v1 * w.z; acc[1][3] += v1 * w.w;
            }
#pragma unroll
            for (int jj = 0; jj < 2; ++jj) {
                int it = ty1 * 2 + jj;
#pragma unroll
                for (int c = 0; c < 4; ++c)
                    hs[it * HM + 4 * tx1 + c] = fmaxf(acc[jj][c] + b1s[4 * tx1 + c], 0.f);
            }
        }
        __syncthreads();
        {
            float acc[4][4];
#pragma unroll
            for (int ii = 0; ii < 4; ++ii)
#pragma unroll
                for (int c = 0; c < 4; ++c) acc[ii][c] = 0.f;
            const float* inp = hs + (ty2 * 4) * HM;
#pragma unroll 2
            for (int k = 0; k < HM; ++k) {
                float4 w = *(const float4*)(W2s + k * DN + 4 * tx2);
#pragma unroll
                for (int ii = 0; ii < 4; ++ii) {
                    float v = inp[ii * HM + k];
                    acc[ii][0] += v * w.x; acc[ii][1] += v * w.y;
                    acc[ii][2] += v * w.z; acc[ii][3] += v * w.w;
                }
            }
#pragma unroll
            for (int ii = 0; ii < 4; ++ii) {
                int i = (tile << 5) + ty2 * 4 + ii;
                if (i < NN) {
                    float* o = out + (size_t)i * DN + 4 * tx2;
#pragma unroll
                    for (int c = 0; c < 4; ++c) o[c] = acc[ii][c] + b2s[4 * tx2 + c];
                }
            }
        }
    }
}

// ===================== launch =====================
extern "C" void kernel_launch(void* const* d_in, const int* in_sizes, int n_in,
                              void* d_out, int out_size) {
    (void)in_sizes; (void)n_in; (void)out_size;
    const float* x  = (const float*)d_in[0];
    const float* ea = (const float*)d_in[1];
    const int*   ei = (const int*)d_in[2];
    const float* Wm = (const float*)d_in[3];
    const float* bm = (const float*)d_in[4];
    const float* Wa = (const float*)d_in[5];
    const float* ba = (const float*)d_in[6];
    const float* We = (const float*)d_in[7];
    const float* be = (const float*)d_in[8];
    const float* W1 = (const float*)d_in[9];
    const float* b1 = (const float*)d_in[10];
    const float* W2 = (const float*)d_in[11];
    const float* b2 = (const float*)d_in[12];
    float* out = (float*)d_out;
    const int* src = ei;
    const int* dst = ei + NE;

    int nsm = 0;
    cudaDeviceGetAttribute(&nsm, cudaDevAttrMultiProcessorCount, 0);
    if (nsm <= 0) nsm = 148;

    const int SM_UPD = (KA * DN + DN + 64 * KA + 64) * 4;
    const int SM_HED = (DN * HM + HM + HM * DN + DN + 32 * DN + 32 * HM) * 4;

    cudaFuncSetAttribute(msg_mma,  cudaFuncAttributeMaxDynamicSharedMemorySize, MS_SMEM);
    cudaFuncSetAttribute(edge_mma, cudaFuncAttributeMaxDynamicSharedMemorySize, ED_SMEM);
    cudaFuncSetAttribute(upd_kernel,  cudaFuncAttributeMaxDynamicSharedMemorySize, SM_UPD);
    cudaFuncSetAttribute(head_kernel, cudaFuncAttributeMaxDynamicSharedMemorySize, SM_HED);

    void *agg_addr = 0, *cnt_addr = 0, *x_addr = 0, *ea_addr = 0;
    cudaGetSymbolAddress(&agg_addr, g_agg);
    cudaGetSymbolAddress(&cnt_addr, g_cnt);
    cudaGetSymbolAddress(&x_addr, g_x);
    cudaGetSymbolAddress(&ea_addr, g_ea);

    cudaMemsetAsync(cnt_addr, 0, NN * sizeof(float));
    cnt_kernel<<<(NE + 255) / 256, 256>>>(dst);

    for (int l = 0; l < 3; ++l) {
        const float* xl  = (l == 0) ? x  : (const float*)x_addr;
        const float* eal = (l == 0) ? ea : (const float*)ea_addr;
        cudaMemsetAsync(agg_addr, 0, (size_t)NN * DN * sizeof(float));
        msg_mma<<<nsm, 512, MS_SMEM>>>(xl, eal, src, dst,
                                       Wm + (size_t)l * (DN + DE) * DN, bm + l * DN);
        upd_kernel<<<nsm, 512, SM_UPD>>>(xl, Wa + (size_t)l * KA * DN, ba + l * DN);
        edge_mma<<<nsm, 512, ED_SMEM>>>(eal, src, dst,
                                        We + (size_t)l * (2 * DN + DE) * DE, be + l * DE);
    }
    head_kernel<<<nsm, 256, SM_HED>>>(W1, b1, W2, b2, out);
}

// round 7
// speedup vs baseline: 5.4943x; 1.3295x over previous
#include <cuda_runtime.h>
#include <cstdint>

#define NN 50000
#define NE 500000
#define DN 128
#define DE 64
#define KA 256
#define HM 64

__device__ float g_x[NN * DN];
__device__ float g_ea[NE * DE];
__device__ float g_agg[NN * DN];
__device__ float g_cnt[NN];

// ===================== helpers =====================
__device__ __forceinline__ uint32_t smem_u32(const void* p) {
    uint32_t a;
    asm("{ .reg .u64 t; cvta.to.shared.u64 t, %1; cvt.u32.u64 %0, t; }" : "=r"(a) : "l"(p));
    return a;
}
#define LDSM4(r0, r1, r2, r3, addr) \
    asm volatile("ldmatrix.sync.aligned.m8n8.x4.shared.b16 {%0,%1,%2,%3}, [%4];" \
                 : "=r"(r0), "=r"(r1), "=r"(r2), "=r"(r3) : "r"(addr))
#define MMA(c, a, b) \
    asm volatile("mma.sync.aligned.m16n8k16.row.col.f32.bf16.bf16.f32 " \
                 "{%0,%1,%2,%3},{%4,%5,%6,%7},{%8,%9},{%0,%1,%2,%3};" \
                 : "+f"((c)[0]), "+f"((c)[1]), "+f"((c)[2]), "+f"((c)[3]) \
                 : "r"((a)[0]), "r"((a)[1]), "r"((a)[2]), "r"((a)[3]), \
                   "r"((b)[0]), "r"((b)[1]))
#define BARG(id) asm volatile("bar.sync %0, %1;" :: "r"(id), "r"(256) : "memory")

__device__ __forceinline__ void splitp(float a, float b, uint32_t& hi, uint32_t& lo) {
    uint32_t ua = __float_as_uint(a), ub = __float_as_uint(b);
    hi = __byte_perm(ua, ub, 0x7632);
    float la = a - __uint_as_float(ua & 0xFFFF0000u);
    float lb = b - __uint_as_float(ub & 0xFFFF0000u);
    lo = __byte_perm(__float_as_uint(la), __float_as_uint(lb), 0x7632);
}

// ===================== cnt =====================
__global__ void cnt_kernel(const int* __restrict__ dst) {
    int e = blockIdx.x * blockDim.x + threadIdx.x;
    if (e < NE) atomicAdd(&g_cnt[dst[e]], 1.0f);
}

// ============ MESSAGE: 2 ping-pong groups x 64-edge subtiles ============
#define MS_P 400
#define MS_WT_H 0
#define MS_WT_L 51200
#define MS_AB 102400
#define MS_BIAS 204800
#define MS_IDX 205312
#define MS_SMEM 206336

__global__ void __launch_bounds__(512, 1)
msg_mma(const float* __restrict__ x, const float* __restrict__ ea,
        const int* __restrict__ src, const int* __restrict__ dst,
        const float* __restrict__ W, const float* __restrict__ bias) {
    extern __shared__ char sm[];
    const uint32_t sb = smem_u32(sm);
    float* bs = (float*)(sm + MS_BIAS);
    const int t = threadIdx.x, lane = t & 31, wid = t >> 5;
    const int g = wid >> 3, w8 = wid & 7, t8 = t & 255;

    for (int i = t; i < 128 * 96; i += 512) {
        int n = i & 127, kp = i >> 7;
        uint32_t h, l;
        splitp(W[(2 * kp) * DN + n], W[(2 * kp + 1) * DN + n], h, l);
        *(uint32_t*)(sm + MS_WT_H + n * MS_P + kp * 4) = h;
        *(uint32_t*)(sm + MS_WT_L + n * MS_P + kp * 4) = l;
    }
    if (t < 128) bs[t] = bias[t];
    __syncthreads();

    const int AH = MS_AB + g * 51200, AL = AH + 25600;
    int* ssrc = (int*)(sm + MS_IDX + g * 512);
    int* sdst = ssrc + 64;
    const int bar = 1 + g;

    const int we = w8 >> 1, wo = w8 & 1;
    const int am = we * 16 + (lane & 15);
    const int ak = (lane >> 4) << 3;
    const int bn0 = wo * 64 + (lane & 7) + ((lane >> 4) << 3);
    const int bk = (lane & 8) ? 8 : 0;
    const int ntiles = (NE + 63) >> 6;

    for (int tile = blockIdx.x * 2 + g; tile < ntiles; tile += gridDim.x * 2) {
        BARG(bar);
        if (t8 < 64) {
            int e = tile * 64 + t8;
            ssrc[t8] = (e < NE) ? src[e] : -1;
            sdst[t8] = (e < NE) ? dst[e] : -1;
        }
        BARG(bar);
        for (int i = t8; i < 64 * 24; i += 256) {
            int row = i / 24, gg = i - row * 24, k0 = gg * 8;
            int s = ssrc[row];
            uint4 H = make_uint4(0, 0, 0, 0), L = H;
            if (s >= 0) {
                const float* p = (k0 < DN) ? x + (size_t)s * DN + k0
                                           : ea + (size_t)(tile * 64 + row) * DE + (k0 - DN);
                float4 v0 = *(const float4*)p, v1 = *(const float4*)(p + 4);
                splitp(v0.x, v0.y, H.x, L.x); splitp(v0.z, v0.w, H.y, L.y);
                splitp(v1.x, v1.y, H.z, L.z); splitp(v1.z, v1.w, H.w, L.w);
            }
            *(uint4*)(sm + AH + row * MS_P + gg * 16) = H;
            *(uint4*)(sm + AL + row * MS_P + gg * 16) = L;
        }
        BARG(bar);

        float c[8][4];
#pragma unroll
        for (int n = 0; n < 8; ++n) { c[n][0] = c[n][1] = c[n][2] = c[n][3] = 0.f; }
#pragma unroll
        for (int ks = 0; ks < 12; ++ks) {
            int k0 = ks * 16;
            uint32_t ah[4], al[4];
            uint32_t aoff = am * MS_P + (k0 + ak) * 2;
            LDSM4(ah[0], ah[1], ah[2], ah[3], sb + AH + aoff);
            LDSM4(al[0], al[1], al[2], al[3], sb + AL + aoff);
            uint32_t Bh[8][2], Bl[8][2];
#pragma unroll
            for (int p = 0; p < 4; ++p) {
                uint32_t boff = (uint32_t)(bn0 + p * 16) * MS_P + (k0 + bk) * 2;
                LDSM4(Bh[2 * p][0], Bh[2 * p][1], Bh[2 * p + 1][0], Bh[2 * p + 1][1],
                      sb + MS_WT_H + boff);
                LDSM4(Bl[2 * p][0], Bl[2 * p][1], Bl[2 * p + 1][0], Bl[2 * p + 1][1],
                      sb + MS_WT_L + boff);
            }
#pragma unroll
            for (int n = 0; n < 8; ++n) MMA(c[n], ah, Bh[n]);
#pragma unroll
            for (int n = 0; n < 8; ++n) MMA(c[n], ah, Bl[n]);
#pragma unroll
            for (int n = 0; n < 8; ++n) MMA(c[n], al, Bh[n]);
        }
        int r0 = we * 16 + (lane >> 2), r1 = r0 + 8;
        int d0 = sdst[r0], d1 = sdst[r1];
#pragma unroll
        for (int n = 0; n < 8; ++n) {
            int col = wo * 64 + n * 8 + (lane & 3) * 2;
            float b0 = bs[col], b1 = bs[col + 1];
            float v;
            if (d0 >= 0) {
                v = c[n][0] + b0; if (v > 0.f) atomicAdd(g_agg + (size_t)d0 * DN + col, v);
                v = c[n][1] + b1; if (v > 0.f) atomicAdd(g_agg + (size_t)d0 * DN + col + 1, v);
            }
            if (d1 >= 0) {
                v = c[n][2] + b0; if (v > 0.f) atomicAdd(g_agg + (size_t)d1 * DN + col, v);
                v = c[n][3] + b1; if (v > 0.f) atomicAdd(g_agg + (size_t)d1 * DN + col + 1, v);
            }
        }
    }
}

// ============ EDGE: 2 ping-pong groups x 32-edge subtiles, split-K ============
#define ED_P 656
#define ED_WT_H 0
#define ED_WT_L 41984
#define ED_GRP 83968
#define ED_BIAS 184320
#define ED_IDX 184576
#define ED_SMEM 185088

__global__ void __launch_bounds__(512, 1)
edge_mma(const float* __restrict__ eain,
         const int* __restrict__ src, const int* __restrict__ dst,
         const float* __restrict__ W, const float* __restrict__ bias) {
    extern __shared__ char sm[];
    const uint32_t sb = smem_u32(sm);
    float* bs = (float*)(sm + ED_BIAS);
    const int t = threadIdx.x, lane = t & 31, wid = t >> 5;
    const int g = wid >> 3, w8 = wid & 7, t8 = t & 255;

    for (int i = t; i < 64 * 160; i += 512) {
        int n = i & 63, kp = i >> 6;
        uint32_t h, l;
        splitp(W[(2 * kp) * DE + n], W[(2 * kp + 1) * DE + n], h, l);
        *(uint32_t*)(sm + ED_WT_H + n * ED_P + kp * 4) = h;
        *(uint32_t*)(sm + ED_WT_L + n * ED_P + kp * 4) = l;
    }
    if (t < 64) bs[t] = bias[t];
    __syncthreads();

    const int AH = ED_GRP + g * 50176, AL = AH + 20992;
    float* P = (float*)(sm + AH + 41984);
    int* ssrc = (int*)(sm + ED_IDX + g * 256);
    int* sdst = ssrc + 32;
    const int bar = 1 + g;

    const int wk = w8 >> 2;
    const int rr = (w8 >> 1) & 1, wo = w8 & 1;
    const int am = rr * 16 + (lane & 15);
    const int ak = (lane >> 4) << 3;
    const int bn0 = wo * 32 + (lane & 7) + ((lane >> 4) << 3);
    const int bk = (lane & 8) ? 8 : 0;
    const int ntiles = (NE + 31) >> 5;

    for (int tile = blockIdx.x * 2 + g; tile < ntiles; tile += gridDim.x * 2) {
        BARG(bar);
        if (t8 < 32) {
            int e = tile * 32 + t8;
            ssrc[t8] = (e < NE) ? src[e] : -1;
            sdst[t8] = (e < NE) ? dst[e] : -1;
        }
        BARG(bar);
        for (int i = t8; i < 32 * 40; i += 256) {
            int row = i / 40, gg = i - row * 40, k0 = gg * 8;
            int s = ssrc[row];
            uint4 H = make_uint4(0, 0, 0, 0), L = H;
            if (s >= 0) {
                const float* p;
                if (k0 < DN)          p = g_x + (size_t)s * DN + k0;
                else if (k0 < 2 * DN) p = g_x + (size_t)sdst[row] * DN + (k0 - DN);
                else                  p = eain + (size_t)(tile * 32 + row) * DE + (k0 - 2 * DN);
                float4 v0 = *(const float4*)p, v1 = *(const float4*)(p + 4);
                splitp(v0.x, v0.y, H.x, L.x); splitp(v0.z, v0.w, H.y, L.y);
                splitp(v1.x, v1.y, H.z, L.z); splitp(v1.z, v1.w, H.w, L.w);
            }
            *(uint4*)(sm + AH + row * ED_P + gg * 16) = H;
            *(uint4*)(sm + AL + row * ED_P + gg * 16) = L;
        }
        BARG(bar);

        float c[4][4];
#pragma unroll
        for (int n = 0; n < 4; ++n) { c[n][0] = c[n][1] = c[n][2] = c[n][3] = 0.f; }
#pragma unroll
        for (int j = 0; j < 10; ++j) {
            int k0 = (wk * 10 + j) * 16;
            uint32_t ah[4], al[4];
            uint32_t aoff = am * ED_P + (k0 + ak) * 2;
            LDSM4(ah[0], ah[1], ah[2], ah[3], sb + AH + aoff);
            LDSM4(al[0], al[1], al[2], al[3], sb + AL + aoff);
            uint32_t Bh[4][2], Bl[4][2];
#pragma unroll
            for (int p = 0; p < 2; ++p) {
                uint32_t boff = (uint32_t)(bn0 + p * 16) * ED_P + (k0 + bk) * 2;
                LDSM4(Bh[2 * p][0], Bh[2 * p][1], Bh[2 * p + 1][0], Bh[2 * p + 1][1],
                      sb + ED_WT_H + boff);
                LDSM4(Bl[2 * p][0], Bl[2 * p][1], Bl[2 * p + 1][0], Bl[2 * p + 1][1],
                      sb + ED_WT_L + boff);
            }
#pragma unroll
            for (int n = 0; n < 4; ++n) MMA(c[n], ah, Bh[n]);
#pragma unroll
            for (int n = 0; n < 4; ++n) MMA(c[n], ah, Bl[n]);
#pragma unroll
            for (int n = 0; n < 4; ++n) MMA(c[n], al, Bh[n]);
        }
        int r0 = rr * 16 + (lane >> 2), r1 = r0 + 8;
        if (wk == 0) {
#pragma unroll
            for (int n = 0; n < 4; ++n) {
                int col = wo * 32 + n * 8 + (lane & 3) * 2;
                *(float2*)(P + r0 * 64 + col) = make_float2(c[n][0], c[n][1]);
                *(float2*)(P + r1 * 64 + col) = make_float2(c[n][2], c[n][3]);
            }
        }
        BARG(bar);
        if (wk == 1) {
            int e0 = tile * 32 + r0, e1 = tile * 32 + r1;
#pragma unroll
            for (int n = 0; n < 4; ++n) {
                int col = wo * 32 + n * 8 + (lane & 3) * 2;
                float b0 = bs[col], b1 = bs[col + 1];
                float2 p0 = *(float2*)(P + r0 * 64 + col);
                float2 p1 = *(float2*)(P + r1 * 64 + col);
                if (e0 < NE) {
                    float2 v = make_float2(fmaxf(c[n][0] + p0.x + b0, 0.f),
                                           fmaxf(c[n][1] + p0.y + b1, 0.f));
                    *(float2*)(g_ea + (size_t)e0 * DE + col) = v;
                }
                if (e1 < NE) {
                    float2 v = make_float2(fmaxf(c[n][2] + p1.x + b0, 0.f),
                                           fmaxf(c[n][3] + p1.y + b1, 0.f));
                    *(float2*)(g_ea + (size_t)e1 * DE + col) = v;
                }
            }
        }
    }
}

// ============ UPDATE (mma): x = L2norm(relu([agg/cnt, x] @ Wa + ba)) ============
// 8 warps, tile = 64 nodes, K=256 (16 ksteps), OUT=128. Single group.
#define UP_P 528
#define UP_WT_H 0
#define UP_WT_L 67584
#define UP_A_H 135168
#define UP_A_L 168960
#define UP_BIAS 202752
#define UP_SINV 203264
#define UP_SSQ 203520          // float[2][64]
#define UP_SMEM 204032

__global__ void __launch_bounds__(256, 1)
upd_mma(const float* __restrict__ xin,
        const float* __restrict__ W, const float* __restrict__ bias) {
    extern __shared__ char sm[];
    const uint32_t sb = smem_u32(sm);
    float* bs = (float*)(sm + UP_BIAS);
    float* sinv = (float*)(sm + UP_SINV);
    float* ssq = (float*)(sm + UP_SSQ);   // [2][64]
    const int t = threadIdx.x, lane = t & 31, wid = t >> 5;

    for (int i = t; i < 128 * 128; i += 256) {
        int n = i & 127, kp = i >> 7;
        uint32_t h, l;
        splitp(W[(2 * kp) * DN + n], W[(2 * kp + 1) * DN + n], h, l);
        *(uint32_t*)(sm + UP_WT_H + n * UP_P + kp * 4) = h;
        *(uint32_t*)(sm + UP_WT_L + n * UP_P + kp * 4) = l;
    }
    if (t < 128) bs[t] = bias[t];

    const int we = wid >> 1, wo = wid & 1;
    const int am = we * 16 + (lane & 15);
    const int ak = (lane >> 4) << 3;
    const int bn0 = wo * 64 + (lane & 7) + ((lane >> 4) << 3);
    const int bk = (lane & 8) ? 8 : 0;
    const int ntiles = (NN + 63) >> 6;

    for (int tile = blockIdx.x; tile < ntiles; tile += gridDim.x) {
        __syncthreads();
        if (t < 64) {
            int i = (tile << 6) + t;
            float c = (i < NN) ? g_cnt[i] : 1.f;
            sinv[t] = 1.f / fmaxf(c, 1.f);
        }
        __syncthreads();
        for (int i = t; i < 64 * 32; i += 256) {
            int row = i >> 5, gg = i & 31, k0 = gg * 8;
            int nd = (tile << 6) + row;
            uint4 H = make_uint4(0, 0, 0, 0), L = H;
            if (nd < NN) {
                float4 v0, v1;
                if (k0 < DN) {
                    float iv = sinv[row];
                    v0 = *(const float4*)(g_agg + (size_t)nd * DN + k0);
                    v1 = *(const float4*)(g_agg + (size_t)nd * DN + k0 + 4);
                    v0.x *= iv; v0.y *= iv; v0.z *= iv; v0.w *= iv;
                    v1.x *= iv; v1.y *= iv; v1.z *= iv; v1.w *= iv;
                } else {
                    v0 = *(const float4*)(xin + (size_t)nd * DN + (k0 - DN));
                    v1 = *(const float4*)(xin + (size_t)nd * DN + (k0 - DN) + 4);
                }
                splitp(v0.x, v0.y, H.x, L.x); splitp(v0.z, v0.w, H.y, L.y);
                splitp(v1.x, v1.y, H.z, L.z); splitp(v1.z, v1.w, H.w, L.w);
            }
            *(uint4*)(sm + UP_A_H + row * UP_P + gg * 16) = H;
            *(uint4*)(sm + UP_A_L + row * UP_P + gg * 16) = L;
        }
        __syncthreads();

        float c[8][4];
#pragma unroll
        for (int n = 0; n < 8; ++n) { c[n][0] = c[n][1] = c[n][2] = c[n][3] = 0.f; }
#pragma unroll
        for (int ks = 0; ks < 16; ++ks) {
            int k0 = ks * 16;
            uint32_t ah[4], al[4];
            uint32_t aoff = am * UP_P + (k0 + ak) * 2;
            LDSM4(ah[0], ah[1], ah[2], ah[3], sb + UP_A_H + aoff);
            LDSM4(al[0], al[1], al[2], al[3], sb + UP_A_L + aoff);
            uint32_t Bh[8][2], Bl[8][2];
#pragma unroll
            for (int p = 0; p < 4; ++p) {
                uint32_t boff = (uint32_t)(bn0 + p * 16) * UP_P + (k0 + bk) * 2;
                LDSM4(Bh[2 * p][0], Bh[2 * p][1], Bh[2 * p + 1][0], Bh[2 * p + 1][1],
                      sb + UP_WT_H + boff);
                LDSM4(Bl[2 * p][0], Bl[2 * p][1], Bl[2 * p + 1][0], Bl[2 * p + 1][1],
                      sb + UP_WT_L + boff);
            }
#pragma unroll
            for (int n = 0; n < 8; ++n) MMA(c[n], ah, Bh[n]);
#pragma unroll
            for (int n = 0; n < 8; ++n) MMA(c[n], ah, Bl[n]);
#pragma unroll
            for (int n = 0; n < 8; ++n) MMA(c[n], al, Bh[n]);
        }
        // epilogue: relu + bias, partial sum-squares, cross-warp norm
        int r0 = we * 16 + (lane >> 2), r1 = r0 + 8;
        float s0 = 0.f, s1 = 0.f;
#pragma unroll
        for (int n = 0; n < 8; ++n) {
            int col = wo * 64 + n * 8 + (lane & 3) * 2;
            float b0 = bs[col], b1 = bs[col + 1];
            c[n][0] = fmaxf(c[n][0] + b0, 0.f);
            c[n][1] = fmaxf(c[n][1] + b1, 0.f);
            c[n][2] = fmaxf(c[n][2] + b0, 0.f);
            c[n][3] = fmaxf(c[n][3] + b1, 0.f);
            s0 += c[n][0] * c[n][0] + c[n][1] * c[n][1];
            s1 += c[n][2] * c[n][2] + c[n][3] * c[n][3];
        }
        s0 += __shfl_xor_sync(0xffffffffu, s0, 1);
        s0 += __shfl_xor_sync(0xffffffffu, s0, 2);
        s1 += __shfl_xor_sync(0xffffffffu, s1, 1);
        s1 += __shfl_xor_sync(0xffffffffu, s1, 2);
        if ((lane & 3) == 0) {
            ssq[wo * 64 + r0] = s0;
            ssq[wo * 64 + r1] = s1;
        }
        __syncthreads();
        float sc0 = 1.f / fmaxf(sqrtf(ssq[r0] + ssq[64 + r0]), 1e-12f);
        float sc1 = 1.f / fmaxf(sqrtf(ssq[r1] + ssq[64 + r1]), 1e-12f);
        int i0 = (tile << 6) + r0, i1 = (tile << 6) + r1;
#pragma unroll
        for (int n = 0; n < 8; ++n) {
            int col = wo * 64 + n * 8 + (lane & 3) * 2;
            if (i0 < NN)
                *(float2*)(g_x + (size_t)i0 * DN + col) =
                    make_float2(c[n][0] * sc0, c[n][1] * sc0);
            if (i1 < NN)
                *(float2*)(g_x + (size_t)i1 * DN + col) =
                    make_float2(c[n][2] * sc1, c[n][3] * sc1);
        }
    }
}

// ===================== HEAD (SIMT) =====================
__global__ void __launch_bounds__(256, 1)
head_kernel(const float* __restrict__ W1, const float* __restrict__ b1,
            const float* __restrict__ W2, const float* __restrict__ b2,
            float* __restrict__ out) {
    extern __shared__ float smf[];
    float* W1s = smf;
    float* b1s = W1s + DN * HM;
    float* W2s = b1s + HM;
    float* b2s = W2s + HM * DN;
    float* ins = b2s + DN;
    float* hs = ins + 32 * DN;
    const int t = threadIdx.x;
    for (int i = t; i < DN * HM; i += 256) W1s[i] = W1[i];
    for (int i = t; i < HM * DN; i += 256) W2s[i] = W2[i];
    if (t < HM) b1s[t] = b1[t];
    if (t < DN) b2s[t] = b2[t];
    const int tx1 = t & 15, ty1 = t >> 4;
    const int tx2 = t & 31, ty2 = t >> 5;
    const int ntiles = (NN + 31) >> 5;
    for (int tile = blockIdx.x; tile < ntiles; tile += gridDim.x) {
        __syncthreads();
        for (int idx = t; idx < 32 * DN; idx += 256) {
            int it = idx >> 7, c = idx & 127;
            int i = (tile << 5) + it;
            ins[idx] = (i < NN) ? g_x[(size_t)i * DN + c] : 0.f;
        }
        __syncthreads();
        {
            float acc[2][4] = {{0, 0, 0, 0}, {0, 0, 0, 0}};
            const float* inp = ins + (ty1 * 2) * DN;
#pragma unroll 2
            for (int k = 0; k < DN; ++k) {
                float4 w = *(const float4*)(W1s + k * HM + 4 * tx1);
                float v0 = inp[k], v1 = inp[DN + k];
                acc[0][0] += v0 * w.x; acc[0][1] += v0 * w.y;
                acc[0][2] += v0 * w.z; acc[0][3] += v0 * w.w;
                acc[1][0] += v1 * w.x; acc[1][1] += v1 * w.y;
                acc[1][2] += v1 * w.z; acc[1][3] += v1 * w.w;
            }
#pragma unroll
            for (int jj = 0; jj < 2; ++jj) {
                int it = ty1 * 2 + jj;
#pragma unroll
                for (int c = 0; c < 4; ++c)
                    hs[it * HM + 4 * tx1 + c] = fmaxf(acc[jj][c] + b1s[4 * tx1 + c], 0.f);
            }
        }
        __syncthreads();
        {
            float acc[4][4];
#pragma unroll
            for (int ii = 0; ii < 4; ++ii)
#pragma unroll
                for (int c = 0; c < 4; ++c) acc[ii][c] = 0.f;
            const float* inp = hs + (ty2 * 4) * HM;
#pragma unroll 2
            for (int k = 0; k < HM; ++k) {
                float4 w = *(const float4*)(W2s + k * DN + 4 * tx2);
#pragma unroll
                for (int ii = 0; ii < 4; ++ii) {
                    float v = inp[ii * HM + k];
                    acc[ii][0] += v * w.x; acc[ii][1] += v * w.y;
                    acc[ii][2] += v * w.z; acc[ii][3] += v * w.w;
                }
            }
#pragma unroll
            for (int ii = 0; ii < 4; ++ii) {
                int i = (tile << 5) + ty2 * 4 + ii;
                if (i < NN) {
                    float* o = out + (size_t)i * DN + 4 * tx2;
#pragma unroll
                    for (int c = 0; c < 4; ++c) o[c] = acc[ii][c] + b2s[4 * tx2 + c];
                }
            }
        }
    }
}

// ===================== launch =====================
extern "C" void kernel_launch(void* const* d_in, const int* in_sizes, int n_in,
                              void* d_out, int out_size) {
    (void)in_sizes; (void)n_in; (void)out_size;
    const float* x  = (const float*)d_in[0];
    const float* ea = (const float*)d_in[1];
    const int*   ei = (const int*)d_in[2];
    const float* Wm = (const float*)d_in[3];
    const float* bm = (const float*)d_in[4];
    const float* Wa = (const float*)d_in[5];
    const float* ba = (const float*)d_in[6];
    const float* We = (const float*)d_in[7];
    const float* be = (const float*)d_in[8];
    const float* W1 = (const float*)d_in[9];
    const float* b1 = (const float*)d_in[10];
    const float* W2 = (const float*)d_in[11];
    const float* b2 = (const float*)d_in[12];
    float* out = (float*)d_out;
    const int* src = ei;
    const int* dst = ei + NE;

    int nsm = 0;
    cudaDeviceGetAttribute(&nsm, cudaDevAttrMultiProcessorCount, 0);
    if (nsm <= 0) nsm = 148;

    const int SM_HED = (DN * HM + HM + HM * DN + DN + 32 * DN + 32 * HM) * 4;

    cudaFuncSetAttribute(msg_mma,  cudaFuncAttributeMaxDynamicSharedMemorySize, MS_SMEM);
    cudaFuncSetAttribute(edge_mma, cudaFuncAttributeMaxDynamicSharedMemorySize, ED_SMEM);
    cudaFuncSetAttribute(upd_mma,  cudaFuncAttributeMaxDynamicSharedMemorySize, UP_SMEM);
    cudaFuncSetAttribute(head_kernel, cudaFuncAttributeMaxDynamicSharedMemorySize, SM_HED);

    void *agg_addr = 0, *cnt_addr = 0, *x_addr = 0, *ea_addr = 0;
    cudaGetSymbolAddress(&agg_addr, g_agg);
    cudaGetSymbolAddress(&cnt_addr, g_cnt);
    cudaGetSymbolAddress(&x_addr, g_x);
    cudaGetSymbolAddress(&ea_addr, g_ea);

    cudaMemsetAsync(cnt_addr, 0, NN * sizeof(float));
    cnt_kernel<<<(NE + 255) / 256, 256>>>(dst);

    for (int l = 0; l < 3; ++l) {
        const float* xl  = (l == 0) ? x  : (const float*)x_addr;
        const float* eal = (l == 0) ? ea : (const float*)ea_addr;
        cudaMemsetAsync(agg_addr, 0, (size_t)NN * DN * sizeof(float));
        msg_mma<<<nsm, 512, MS_SMEM>>>(xl, eal, src, dst,
                                       Wm + (size_t)l * (DN + DE) * DN, bm + l * DN);
        upd_mma<<<nsm, 256, UP_SMEM>>>(xl, Wa + (size_t)l * KA * DN, ba + l * DN);
        edge_mma<<<nsm, 512, ED_SMEM>>>(eal, src, dst,
                                        We + (size_t)l * (2 * DN + DE) * DE, be + l * DE);
    }
    head_kernel<<<nsm, 256, SM_HED>>>(W1, b1, W2, b2, out);
}

// round 8
// speedup vs baseline: 7.2000x; 1.3105x over previous
#include <cuda_runtime.h>
#include <cstdint>

#define NN 50000
#define NE 500000
#define DN 128
#define DE 64
#define KA 256
#define HM 64

__device__ float g_x[NN * DN];
__device__ float g_ea[NE * DE];
__device__ float g_agg[NN * DN];
__device__ float g_cnt[NN];
__device__ float g_xw[NN * DN];   // x @ Wm[0:128]  (msg node part)
__device__ float g_xe[NN * DN];   // x @ [We[0:128] | We[128:256]]  (edge node parts)

// ===================== helpers =====================
__device__ __forceinline__ uint32_t smem_u32(const void* p) {
    uint32_t a;
    asm("{ .reg .u64 t; cvta.to.shared.u64 t, %1; cvt.u32.u64 %0, t; }" : "=r"(a) : "l"(p));
    return a;
}
#define LDSM4(r0, r1, r2, r3, addr) \
    asm volatile("ldmatrix.sync.aligned.m8n8.x4.shared.b16 {%0,%1,%2,%3}, [%4];" \
                 : "=r"(r0), "=r"(r1), "=r"(r2), "=r"(r3) : "r"(addr))
#define MMA(c, a, b) \
    asm volatile("mma.sync.aligned.m16n8k16.row.col.f32.bf16.bf16.f32 " \
                 "{%0,%1,%2,%3},{%4,%5,%6,%7},{%8,%9},{%0,%1,%2,%3};" \
                 : "+f"((c)[0]), "+f"((c)[1]), "+f"((c)[2]), "+f"((c)[3]) \
                 : "r"((a)[0]), "r"((a)[1]), "r"((a)[2]), "r"((a)[3]), \
                   "r"((b)[0]), "r"((b)[1]))
#define BARG(id) asm volatile("bar.sync %0, %1;" :: "r"(id), "r"(256) : "memory")

__device__ __forceinline__ void splitp(float a, float b, uint32_t& hi, uint32_t& lo) {
    uint32_t ua = __float_as_uint(a), ub = __float_as_uint(b);
    hi = __byte_perm(ua, ub, 0x7632);
    float la = a - __uint_as_float(ua & 0xFFFF0000u);
    float lb = b - __uint_as_float(ub & 0xFFFF0000u);
    lo = __byte_perm(__float_as_uint(la), __float_as_uint(lb), 0x7632);
}

// ===================== cnt =====================
__global__ void cnt_kernel(const int* __restrict__ dst) {
    int e = blockIdx.x * blockDim.x + threadIdx.x;
    if (e < NE) atomicAdd(&g_cnt[dst[e]], 1.0f);
}

// ============ NODE MM: out[50K,128] = xin[50K,128] @ W(mode) ============
// mode 0: W(k,n) = Wp[k*128+n]   (pre_msg: Wm rows 0..127)
// mode 1: W(k,n) = n<64 ? Wp[k*64+n] : Wp[(128+k)*64+n-64]   (pre_edge)
#define NM_P 272
#define NM_WT_H 0
#define NM_WT_L 34816
#define NM_A_H 69632
#define NM_A_L 87040
#define NM_SMEM 104448

__global__ void __launch_bounds__(256, 1)
node_mm(const float* __restrict__ xin, const float* __restrict__ Wp,
        int mode, float* __restrict__ out) {
    extern __shared__ char sm[];
    const uint32_t sb = smem_u32(sm);
    const int t = threadIdx.x, lane = t & 31, wid = t >> 5;

    for (int i = t; i < 128 * 64; i += 256) {
        int n = i & 127, kp = i >> 7, k = 2 * kp;
        float w0, w1;
        if (mode == 0) { w0 = Wp[k * 128 + n]; w1 = Wp[(k + 1) * 128 + n]; }
        else {
            if (n < 64) { w0 = Wp[k * 64 + n]; w1 = Wp[(k + 1) * 64 + n]; }
            else { w0 = Wp[(128 + k) * 64 + n - 64]; w1 = Wp[(129 + k) * 64 + n - 64]; }
        }
        uint32_t h, l;
        splitp(w0, w1, h, l);
        *(uint32_t*)(sm + NM_WT_H + n * NM_P + kp * 4) = h;
        *(uint32_t*)(sm + NM_WT_L + n * NM_P + kp * 4) = l;
    }

    const int we = wid >> 1, wo = wid & 1;
    const int am = we * 16 + (lane & 15);
    const int ak = (lane >> 4) << 3;
    const int bn0 = wo * 64 + (lane & 7) + ((lane >> 4) << 3);
    const int bk = (lane & 8) ? 8 : 0;
    const int ntiles = (NN + 63) >> 6;

    for (int tile = blockIdx.x; tile < ntiles; tile += gridDim.x) {
        __syncthreads();
        for (int i = t; i < 64 * 16; i += 256) {
            int row = i >> 4, gg = i & 15, k0 = gg * 8;
            int nd = (tile << 6) + row;
            uint4 H = make_uint4(0, 0, 0, 0), L = H;
            if (nd < NN) {
                float4 v0 = *(const float4*)(xin + (size_t)nd * DN + k0);
                float4 v1 = *(const float4*)(xin + (size_t)nd * DN + k0 + 4);
                splitp(v0.x, v0.y, H.x, L.x); splitp(v0.z, v0.w, H.y, L.y);
                splitp(v1.x, v1.y, H.z, L.z); splitp(v1.z, v1.w, H.w, L.w);
            }
            *(uint4*)(sm + NM_A_H + row * NM_P + gg * 16) = H;
            *(uint4*)(sm + NM_A_L + row * NM_P + gg * 16) = L;
        }
        __syncthreads();

        float c[8][4];
#pragma unroll
        for (int n = 0; n < 8; ++n) { c[n][0] = c[n][1] = c[n][2] = c[n][3] = 0.f; }
#pragma unroll
        for (int ks = 0; ks < 8; ++ks) {
            int k0 = ks * 16;
            uint32_t ah[4], al[4];
            uint32_t aoff = am * NM_P + (k0 + ak) * 2;
            LDSM4(ah[0], ah[1], ah[2], ah[3], sb + NM_A_H + aoff);
            LDSM4(al[0], al[1], al[2], al[3], sb + NM_A_L + aoff);
            uint32_t Bh[8][2], Bl[8][2];
#pragma unroll
            for (int p = 0; p < 4; ++p) {
                uint32_t boff = (uint32_t)(bn0 + p * 16) * NM_P + (k0 + bk) * 2;
                LDSM4(Bh[2 * p][0], Bh[2 * p][1], Bh[2 * p + 1][0], Bh[2 * p + 1][1],
                      sb + NM_WT_H + boff);
                LDSM4(Bl[2 * p][0], Bl[2 * p][1], Bl[2 * p + 1][0], Bl[2 * p + 1][1],
                      sb + NM_WT_L + boff);
            }
#pragma unroll
            for (int n = 0; n < 8; ++n) MMA(c[n], ah, Bh[n]);
#pragma unroll
            for (int n = 0; n < 8; ++n) MMA(c[n], ah, Bl[n]);
#pragma unroll
            for (int n = 0; n < 8; ++n) MMA(c[n], al, Bh[n]);
        }
        int r0 = we * 16 + (lane >> 2), r1 = r0 + 8;
        int i0 = (tile << 6) + r0, i1 = (tile << 6) + r1;
#pragma unroll
        for (int n = 0; n < 8; ++n) {
            int col = wo * 64 + n * 8 + (lane & 3) * 2;
            if (i0 < NN)
                *(float2*)(out + (size_t)i0 * DN + col) = make_float2(c[n][0], c[n][1]);
            if (i1 < NN)
                *(float2*)(out + (size_t)i1 * DN + col) = make_float2(c[n][2], c[n][3]);
        }
    }
}

// ============ MESSAGE: relu(xw[src] + ea@Wm2 + bm) -> atomic agg ============
// 2 ping-pong groups x 64-edge subtiles. K=64, OUT=128.
#define MP 144
#define MS_WT_H 0
#define MS_WT_L 18432
#define MS_GRP 36864          // + g*52736
#define MS_G_SZ 52736         // A_H 9216 | A_L 9216 | XW 33792 | idx 512
#define MS_BIAS 142336
#define MS_SMEM 142848

__global__ void __launch_bounds__(512, 1)
msg_mma(const float* __restrict__ ea,
        const int* __restrict__ src, const int* __restrict__ dst,
        const float* __restrict__ W, const float* __restrict__ bias) {
    extern __shared__ char sm[];
    const uint32_t sb = smem_u32(sm);
    float* bs = (float*)(sm + MS_BIAS);
    const int t = threadIdx.x, lane = t & 31, wid = t >> 5;
    const int g = wid >> 3, w8 = wid & 7, t8 = t & 255;

    for (int i = t; i < 128 * 32; i += 512) {
        int n = i & 127, kp = i >> 7;
        uint32_t h, l;
        splitp(W[(2 * kp) * DN + n], W[(2 * kp + 1) * DN + n], h, l);
        *(uint32_t*)(sm + MS_WT_H + n * MP + kp * 4) = h;
        *(uint32_t*)(sm + MS_WT_L + n * MP + kp * 4) = l;
    }
    if (t < 128) bs[t] = bias[t];
    __syncthreads();

    const int GRP = MS_GRP + g * MS_G_SZ;
    const int AH = GRP, AL = GRP + 9216;
    float* xws = (float*)(sm + GRP + 18432);        // 64 x 132 fp32
    int* ssrc = (int*)(sm + GRP + 52224);
    int* sdst = ssrc + 64;
    const int bar = 1 + g;

    const int we = w8 >> 1, wo = w8 & 1;
    const int am = we * 16 + (lane & 15);
    const int ak = (lane >> 4) << 3;
    const int bn0 = wo * 64 + (lane & 7) + ((lane >> 4) << 3);
    const int bk = (lane & 8) ? 8 : 0;
    const int ntiles = (NE + 63) >> 6;

    for (int tile = blockIdx.x * 2 + g; tile < ntiles; tile += gridDim.x * 2) {
        BARG(bar);
        if (t8 < 64) {
            int e = tile * 64 + t8;
            ssrc[t8] = (e < NE) ? src[e] : -1;
            sdst[t8] = (e < NE) ? dst[e] : -1;
        }
        // ea copy+split (coalesced, edge-indexed)
        for (int i = t8; i < 64 * 8; i += 256) {
            int row = i >> 3, gg = i & 7, k0 = gg * 8;
            int e = tile * 64 + row;
            uint4 H = make_uint4(0, 0, 0, 0), L = H;
            if (e < NE) {
                float4 v0 = *(const float4*)(ea + (size_t)e * DE + k0);
                float4 v1 = *(const float4*)(ea + (size_t)e * DE + k0 + 4);
                splitp(v0.x, v0.y, H.x, L.x); splitp(v0.z, v0.w, H.y, L.y);
                splitp(v1.x, v1.y, H.z, L.z); splitp(v1.z, v1.w, H.w, L.w);
            }
            *(uint4*)(sm + AH + row * MP + gg * 16) = H;
            *(uint4*)(sm + AL + row * MP + gg * 16) = L;
        }
        BARG(bar);
        // xw gather (needs ssrc)
        for (int i = t8; i < 64 * 32; i += 256) {
            int row = i >> 5, q = i & 31;
            int s = ssrc[row];
            if (s >= 0)
                *(float4*)(xws + row * 132 + q * 4) =
                    *(const float4*)(g_xw + (size_t)s * DN + q * 4);
        }
        BARG(bar);

        float c[8][4];
#pragma unroll
        for (int n = 0; n < 8; ++n) { c[n][0] = c[n][1] = c[n][2] = c[n][3] = 0.f; }
#pragma unroll
        for (int ks = 0; ks < 4; ++ks) {
            int k0 = ks * 16;
            uint32_t ah[4], al[4];
            uint32_t aoff = am * MP + (k0 + ak) * 2;
            LDSM4(ah[0], ah[1], ah[2], ah[3], sb + AH + aoff);
            LDSM4(al[0], al[1], al[2], al[3], sb + AL + aoff);
            uint32_t Bh[8][2], Bl[8][2];
#pragma unroll
            for (int p = 0; p < 4; ++p) {
                uint32_t boff = (uint32_t)(bn0 + p * 16) * MP + (k0 + bk) * 2;
                LDSM4(Bh[2 * p][0], Bh[2 * p][1], Bh[2 * p + 1][0], Bh[2 * p + 1][1],
                      sb + MS_WT_H + boff);
                LDSM4(Bl[2 * p][0], Bl[2 * p][1], Bl[2 * p + 1][0], Bl[2 * p + 1][1],
                      sb + MS_WT_L + boff);
            }
#pragma unroll
            for (int n = 0; n < 8; ++n) MMA(c[n], ah, Bh[n]);
#pragma unroll
            for (int n = 0; n < 8; ++n) MMA(c[n], ah, Bl[n]);
#pragma unroll
            for (int n = 0; n < 8; ++n) MMA(c[n], al, Bh[n]);
        }
        int r0 = we * 16 + (lane >> 2), r1 = r0 + 8;
        int d0 = sdst[r0], d1 = sdst[r1];
#pragma unroll
        for (int n = 0; n < 8; ++n) {
            int col = wo * 64 + n * 8 + (lane & 3) * 2;
            float b0 = bs[col], b1 = bs[col + 1];
            float v;
            if (d0 >= 0) {
                v = c[n][0] + xws[r0 * 132 + col] + b0;
                if (v > 0.f) atomicAdd(g_agg + (size_t)d0 * DN + col, v);
                v = c[n][1] + xws[r0 * 132 + col + 1] + b1;
                if (v > 0.f) atomicAdd(g_agg + (size_t)d0 * DN + col + 1, v);
            }
            if (d1 >= 0) {
                v = c[n][2] + xws[r1 * 132 + col] + b0;
                if (v > 0.f) atomicAdd(g_agg + (size_t)d1 * DN + col, v);
                v = c[n][3] + xws[r1 * 132 + col + 1] + b1;
                if (v > 0.f) atomicAdd(g_agg + (size_t)d1 * DN + col + 1, v);
            }
        }
    }
}

// ============ EDGE: relu(xe1[src] + xe2[dst] + ea@We3 + be) ============
// 2 ping-pong groups x 64-edge subtiles. K=64, OUT=64.
#define EP 144
#define ED_WT_H 0
#define ED_WT_L 9216
#define ED_GRP 18432          // + g*53760
#define ED_G_SZ 53760         // A_H 9216 | A_L 9216 | XE1 17408 | XE2 17408 | idx 512
#define ED_BIAS 125952
#define ED_SMEM 126464

__global__ void __launch_bounds__(512, 1)
edge_mma(const float* __restrict__ ea,
         const int* __restrict__ src, const int* __restrict__ dst,
         const float* __restrict__ W, const float* __restrict__ bias) {
    extern __shared__ char sm[];
    const uint32_t sb = smem_u32(sm);
    float* bs = (float*)(sm + ED_BIAS);
    const int t = threadIdx.x, lane = t & 31, wid = t >> 5;
    const int g = wid >> 3, w8 = wid & 7, t8 = t & 255;

    for (int i = t; i < 64 * 32; i += 512) {
        int n = i & 63, kp = i >> 6;
        uint32_t h, l;
        splitp(W[(2 * kp) * DE + n], W[(2 * kp + 1) * DE + n], h, l);
        *(uint32_t*)(sm + ED_WT_H + n * EP + kp * 4) = h;
        *(uint32_t*)(sm + ED_WT_L + n * EP + kp * 4) = l;
    }
    if (t < 64) bs[t] = bias[t];
    __syncthreads();

    const int GRP = ED_GRP + g * ED_G_SZ;
    const int AH = GRP, AL = GRP + 9216;
    float* xe1s = (float*)(sm + GRP + 18432);   // 64 x 68 fp32
    float* xe2s = (float*)(sm + GRP + 35840);   // 64 x 68 fp32
    int* ssrc = (int*)(sm + GRP + 53248);
    int* sdst = ssrc + 64;
    const int bar = 1 + g;

    const int we = w8 >> 1, wo = w8 & 1;
    const int am = we * 16 + (lane & 15);
    const int ak = (lane >> 4) << 3;
    const int bn0 = wo * 32 + (lane & 7) + ((lane >> 4) << 3);
    const int bk = (lane & 8) ? 8 : 0;
    const int ntiles = (NE + 63) >> 6;

    for (int tile = blockIdx.x * 2 + g; tile < ntiles; tile += gridDim.x * 2) {
        BARG(bar);
        if (t8 < 64) {
            int e = tile * 64 + t8;
            ssrc[t8] = (e < NE) ? src[e] : -1;
            sdst[t8] = (e < NE) ? dst[e] : -1;
        }
        for (int i = t8; i < 64 * 8; i += 256) {
            int row = i >> 3, gg = i & 7, k0 = gg * 8;
            int e = tile * 64 + row;
            uint4 H = make_uint4(0, 0, 0, 0), L = H;
            if (e < NE) {
                float4 v0 = *(const float4*)(ea + (size_t)e * DE + k0);
                float4 v1 = *(const float4*)(ea + (size_t)e * DE + k0 + 4);
                splitp(v0.x, v0.y, H.x, L.x); splitp(v0.z, v0.w, H.y, L.y);
                splitp(v1.x, v1.y, H.z, L.z); splitp(v1.z, v1.w, H.w, L.w);
            }
            *(uint4*)(sm + AH + row * EP + gg * 16) = H;
            *(uint4*)(sm + AL + row * EP + gg * 16) = L;
        }
        BARG(bar);
        for (int i = t8; i < 64 * 16; i += 256) {
            int row = i >> 4, q = i & 15;
            int s = ssrc[row], d = sdst[row];
            if (s >= 0) {
                *(float4*)(xe1s + row * 68 + q * 4) =
                    *(const float4*)(g_xe + (size_t)s * DN + q * 4);
                *(float4*)(xe2s + row * 68 + q * 4) =
                    *(const float4*)(g_xe + (size_t)d * DN + 64 + q * 4);
            }
        }
        BARG(bar);

        float c[4][4];
#pragma unroll
        for (int n = 0; n < 4; ++n) { c[n][0] = c[n][1] = c[n][2] = c[n][3] = 0.f; }
#pragma unroll
        for (int ks = 0; ks < 4; ++ks) {
            int k0 = ks * 16;
            uint32_t ah[4], al[4];
            uint32_t aoff = am * EP + (k0 + ak) * 2;
            LDSM4(ah[0], ah[1], ah[2], ah[3], sb + AH + aoff);
            LDSM4(al[0], al[1], al[2], al[3], sb + AL + aoff);
            uint32_t Bh[4][2], Bl[4][2];
#pragma unroll
            for (int p = 0; p < 2; ++p) {
                uint32_t boff = (uint32_t)(bn0 + p * 16) * EP + (k0 + bk) * 2;
                LDSM4(Bh[2 * p][0], Bh[2 * p][1], Bh[2 * p + 1][0], Bh[2 * p + 1][1],
                      sb + ED_WT_H + boff);
                LDSM4(Bl[2 * p][0], Bl[2 * p][1], Bl[2 * p + 1][0], Bl[2 * p + 1][1],
                      sb + ED_WT_L + boff);
            }
#pragma unroll
            for (int n = 0; n < 4; ++n) MMA(c[n], ah, Bh[n]);
#pragma unroll
            for (int n = 0; n < 4; ++n) MMA(c[n], ah, Bl[n]);
#pragma unroll
            for (int n = 0; n < 4; ++n) MMA(c[n], al, Bh[n]);
        }
        int r0 = we * 16 + (lane >> 2), r1 = r0 + 8;
        int e0 = tile * 64 + r0, e1 = tile * 64 + r1;
#pragma unroll
        for (int n = 0; n < 4; ++n) {
            int col = wo * 32 + n * 8 + (lane & 3) * 2;
            float b0 = bs[col], b1 = bs[col + 1];
            if (e0 < NE) {
                float2 v = make_float2(
                    fmaxf(c[n][0] + xe1s[r0 * 68 + col] + xe2s[r0 * 68 + col] + b0, 0.f),
                    fmaxf(c[n][1] + xe1s[r0 * 68 + col + 1] + xe2s[r0 * 68 + col + 1] + b1, 0.f));
                *(float2*)(g_ea + (size_t)e0 * DE + col) = v;
            }
            if (e1 < NE) {
                float2 v = make_float2(
                    fmaxf(c[n][2] + xe1s[r1 * 68 + col] + xe2s[r1 * 68 + col] + b0, 0.f),
                    fmaxf(c[n][3] + xe1s[r1 * 68 + col + 1] + xe2s[r1 * 68 + col + 1] + b1, 0.f));
                *(float2*)(g_ea + (size_t)e1 * DE + col) = v;
            }
        }
    }
}

// ============ UPDATE (mma, proven) ============
#define UP_P 528
#define UP_WT_H 0
#define UP_WT_L 67584
#define UP_A_H 135168
#define UP_A_L 168960
#define UP_BIAS 202752
#define UP_SINV 203264
#define UP_SSQ 203520
#define UP_SMEM 204032

__global__ void __launch_bounds__(256, 1)
upd_mma(const float* __restrict__ xin,
        const float* __restrict__ W, const float* __restrict__ bias) {
    extern __shared__ char sm[];
    const uint32_t sb = smem_u32(sm);
    float* bs = (float*)(sm + UP_BIAS);
    float* sinv = (float*)(sm + UP_SINV);
    float* ssq = (float*)(sm + UP_SSQ);
    const int t = threadIdx.x, lane = t & 31, wid = t >> 5;

    for (int i = t; i < 128 * 128; i += 256) {
        int n = i & 127, kp = i >> 7;
        uint32_t h, l;
        splitp(W[(2 * kp) * DN + n], W[(2 * kp + 1) * DN + n], h, l);
        *(uint32_t*)(sm + UP_WT_H + n * UP_P + kp * 4) = h;
        *(uint32_t*)(sm + UP_WT_L + n * UP_P + kp * 4) = l;
    }
    if (t < 128) bs[t] = bias[t];

    const int we = wid >> 1, wo = wid & 1;
    const int am = we * 16 + (lane & 15);
    const int ak = (lane >> 4) << 3;
    const int bn0 = wo * 64 + (lane & 7) + ((lane >> 4) << 3);
    const int bk = (lane & 8) ? 8 : 0;
    const int ntiles = (NN + 63) >> 6;

    for (int tile = blockIdx.x; tile < ntiles; tile += gridDim.x) {
        __syncthreads();
        if (t < 64) {
            int i = (tile << 6) + t;
            float c = (i < NN) ? g_cnt[i] : 1.f;
            sinv[t] = 1.f / fmaxf(c, 1.f);
        }
        __syncthreads();
        for (int i = t; i < 64 * 32; i += 256) {
            int row = i >> 5, gg = i & 31, k0 = gg * 8;
            int nd = (tile << 6) + row;
            uint4 H = make_uint4(0, 0, 0, 0), L = H;
            if (nd < NN) {
                float4 v0, v1;
                if (k0 < DN) {
                    float iv = sinv[row];
                    v0 = *(const float4*)(g_agg + (size_t)nd * DN + k0);
                    v1 = *(const float4*)(g_agg + (size_t)nd * DN + k0 + 4);
                    v0.x *= iv; v0.y *= iv; v0.z *= iv; v0.w *= iv;
                    v1.x *= iv; v1.y *= iv; v1.z *= iv; v1.w *= iv;
                } else {
                    v0 = *(const float4*)(xin + (size_t)nd * DN + (k0 - DN));
                    v1 = *(const float4*)(xin + (size_t)nd * DN + (k0 - DN) + 4);
                }
                splitp(v0.x, v0.y, H.x, L.x); splitp(v0.z, v0.w, H.y, L.y);
                splitp(v1.x, v1.y, H.z, L.z); splitp(v1.z, v1.w, H.w, L.w);
            }
            *(uint4*)(sm + UP_A_H + row * UP_P + gg * 16) = H;
            *(uint4*)(sm + UP_A_L + row * UP_P + gg * 16) = L;
        }
        __syncthreads();

        float c[8][4];
#pragma unroll
        for (int n = 0; n < 8; ++n) { c[n][0] = c[n][1] = c[n][2] = c[n][3] = 0.f; }
#pragma unroll
        for (int ks = 0; ks < 16; ++ks) {
            int k0 = ks * 16;
            uint32_t ah[4], al[4];
            uint32_t aoff = am * UP_P + (k0 + ak) * 2;
            LDSM4(ah[0], ah[1], ah[2], ah[3], sb + UP_A_H + aoff);
            LDSM4(al[0], al[1], al[2], al[3], sb + UP_A_L + aoff);
            uint32_t Bh[8][2], Bl[8][2];
#pragma unroll
            for (int p = 0; p < 4; ++p) {
                uint32_t boff = (uint32_t)(bn0 + p * 16) * UP_P + (k0 + bk) * 2;
                LDSM4(Bh[2 * p][0], Bh[2 * p][1], Bh[2 * p + 1][0], Bh[2 * p + 1][1],
                      sb + UP_WT_H + boff);
                LDSM4(Bl[2 * p][0], Bl[2 * p][1], Bl[2 * p + 1][0], Bl[2 * p + 1][1],
                      sb + UP_WT_L + boff);
            }
#pragma unroll
            for (int n = 0; n < 8; ++n) MMA(c[n], ah, Bh[n]);
#pragma unroll
            for (int n = 0; n < 8; ++n) MMA(c[n], ah, Bl[n]);
#pragma unroll
            for (int n = 0; n < 8; ++n) MMA(c[n], al, Bh[n]);
        }
        int r0 = we * 16 + (lane >> 2), r1 = r0 + 8;
        float s0 = 0.f, s1 = 0.f;
#pragma unroll
        for (int n = 0; n < 8; ++n) {
            int col = wo * 64 + n * 8 + (lane & 3) * 2;
            float b0 = bs[col], b1 = bs[col + 1];
            c[n][0] = fmaxf(c[n][0] + b0, 0.f);
            c[n][1] = fmaxf(c[n][1] + b1, 0.f);
            c[n][2] = fmaxf(c[n][2] + b0, 0.f);
            c[n][3] = fmaxf(c[n][3] + b1, 0.f);
            s0 += c[n][0] * c[n][0] + c[n][1] * c[n][1];
            s1 += c[n][2] * c[n][2] + c[n][3] * c[n][3];
        }
        s0 += __shfl_xor_sync(0xffffffffu, s0, 1);
        s0 += __shfl_xor_sync(0xffffffffu, s0, 2);
        s1 += __shfl_xor_sync(0xffffffffu, s1, 1);
        s1 += __shfl_xor_sync(0xffffffffu, s1, 2);
        if ((lane & 3) == 0) {
            ssq[wo * 64 + r0] = s0;
            ssq[wo * 64 + r1] = s1;
        }
        __syncthreads();
        float sc0 = 1.f / fmaxf(sqrtf(ssq[r0] + ssq[64 + r0]), 1e-12f);
        float sc1 = 1.f / fmaxf(sqrtf(ssq[r1] + ssq[64 + r1]), 1e-12f);
        int i0 = (tile << 6) + r0, i1 = (tile << 6) + r1;
#pragma unroll
        for (int n = 0; n < 8; ++n) {
            int col = wo * 64 + n * 8 + (lane & 3) * 2;
            if (i0 < NN)
                *(float2*)(g_x + (size_t)i0 * DN + col) =
                    make_float2(c[n][0] * sc0, c[n][1] * sc0);
            if (i1 < NN)
                *(float2*)(g_x + (size_t)i1 * DN + col) =
                    make_float2(c[n][2] * sc1, c[n][3] * sc1);
        }
    }
}

// ===================== HEAD (SIMT) =====================
__global__ void __launch_bounds__(256, 1)
head_kernel(const float* __restrict__ W1, const float* __restrict__ b1,
            const float* __restrict__ W2, const float* __restrict__ b2,
            float* __restrict__ out) {
    extern __shared__ float smf[];
    float* W1s = smf;
    float* b1s = W1s + DN * HM;
    float* W2s = b1s + HM;
    float* b2s = W2s + HM * DN;
    float* ins = b2s + DN;
    float* hs = ins + 32 * DN;
    const int t = threadIdx.x;
    for (int i = t; i < DN * HM; i += 256) W1s[i] = W1[i];
    for (int i = t; i < HM * DN; i += 256) W2s[i] = W2[i];
    if (t < HM) b1s[t] = b1[t];
    if (t < DN) b2s[t] = b2[t];
    const int tx1 = t & 15, ty1 = t >> 4;
    const int tx2 = t & 31, ty2 = t >> 5;
    const int ntiles = (NN + 31) >> 5;
    for (int tile = blockIdx.x; tile < ntiles; tile += gridDim.x) {
        __syncthreads();
        for (int idx = t; idx < 32 * DN; idx += 256) {
            int it = idx >> 7, c = idx & 127;
            int i = (tile << 5) + it;
            ins[idx] = (i < NN) ? g_x[(size_t)i * DN + c] : 0.f;
        }
        __syncthreads();
        {
            float acc[2][4] = {{0, 0, 0, 0}, {0, 0, 0, 0}};
            const float* inp = ins + (ty1 * 2) * DN;
#pragma unroll 2
            for (int k = 0; k < DN; ++k) {
                float4 w = *(const float4*)(W1s + k * HM + 4 * tx1);
                float v0 = inp[k], v1 = inp[DN + k];
                acc[0][0] += v0 * w.x; acc[0][1] += v0 * w.y;
                acc[0][2] += v0 * w.z; acc[0][3] += v0 * w.w;
                acc[1][0] += v1 * w.x; acc[1][1] += v1 * w.y;
                acc[1][2] += v1 * w.z; acc[1][3] += v1 * w.w;
            }
#pragma unroll
            for (int jj = 0; jj < 2; ++jj) {
                int it = ty1 * 2 + jj;
#pragma unroll
                for (int c = 0; c < 4; ++c)
                    hs[it * HM + 4 * tx1 + c] = fmaxf(acc[jj][c] + b1s[4 * tx1 + c], 0.f);
            }
        }
        __syncthreads();
        {
            float acc[4][4];
#pragma unroll
            for (int ii = 0; ii < 4; ++ii)
#pragma unroll
                for (int c = 0; c < 4; ++c) acc[ii][c] = 0.f;
            const float* inp = hs + (ty2 * 4) * HM;
#pragma unroll 2
            for (int k = 0; k < HM; ++k) {
                float4 w = *(const float4*)(W2s + k * DN + 4 * tx2);
#pragma unroll
                for (int ii = 0; ii < 4; ++ii) {
                    float v = inp[ii * HM + k];
                    acc[ii][0] += v * w.x; acc[ii][1] += v * w.y;
                    acc[ii][2] += v * w.z; acc[ii][3] += v * w.w;
                }
            }
#pragma unroll
            for (int ii = 0; ii < 4; ++ii) {
                int i = (tile << 5) + ty2 * 4 + ii;
                if (i < NN) {
                    float* o = out + (size_t)i * DN + 4 * tx2;
#pragma unroll
                    for (int c = 0; c < 4; ++c) o[c] = acc[ii][c] + b2s[4 * tx2 + c];
                }
            }
        }
    }
}

// ===================== launch =====================
extern "C" void kernel_launch(void* const* d_in, const int* in_sizes, int n_in,
                              void* d_out, int out_size) {
    (void)in_sizes; (void)n_in; (void)out_size;
    const float* x  = (const float*)d_in[0];
    const float* ea = (const float*)d_in[1];
    const int*   ei = (const int*)d_in[2];
    const float* Wm = (const float*)d_in[3];
    const float* bm = (const float*)d_in[4];
    const float* Wa = (const float*)d_in[5];
    const float* ba = (const float*)d_in[6];
    const float* We = (const float*)d_in[7];
    const float* be = (const float*)d_in[8];
    const float* W1 = (const float*)d_in[9];
    const float* b1 = (const float*)d_in[10];
    const float* W2 = (const float*)d_in[11];
    const float* b2 = (const float*)d_in[12];
    float* out = (float*)d_out;
    const int* src = ei;
    const int* dst = ei + NE;

    int nsm = 0;
    cudaDeviceGetAttribute(&nsm, cudaDevAttrMultiProcessorCount, 0);
    if (nsm <= 0) nsm = 148;

    const int SM_HED = (DN * HM + HM + HM * DN + DN + 32 * DN + 32 * HM) * 4;

    cudaFuncSetAttribute(node_mm,  cudaFuncAttributeMaxDynamicSharedMemorySize, NM_SMEM);
    cudaFuncSetAttribute(msg_mma,  cudaFuncAttributeMaxDynamicSharedMemorySize, MS_SMEM);
    cudaFuncSetAttribute(edge_mma, cudaFuncAttributeMaxDynamicSharedMemorySize, ED_SMEM);
    cudaFuncSetAttribute(upd_mma,  cudaFuncAttributeMaxDynamicSharedMemorySize, UP_SMEM);
    cudaFuncSetAttribute(head_kernel, cudaFuncAttributeMaxDynamicSharedMemorySize, SM_HED);

    void *agg_addr = 0, *cnt_addr = 0, *x_addr = 0, *ea_addr = 0;
    void *xw_addr = 0, *xe_addr = 0;
    cudaGetSymbolAddress(&agg_addr, g_agg);
    cudaGetSymbolAddress(&cnt_addr, g_cnt);
    cudaGetSymbolAddress(&x_addr, g_x);
    cudaGetSymbolAddress(&ea_addr, g_ea);
    cudaGetSymbolAddress(&xw_addr, g_xw);
    cudaGetSymbolAddress(&xe_addr, g_xe);

    cudaMemsetAsync(cnt_addr, 0, NN * sizeof(float));
    cnt_kernel<<<(NE + 255) / 256, 256>>>(dst);

    for (int l = 0; l < 3; ++l) {
        const float* xl  = (l == 0) ? x  : (const float*)x_addr;
        const float* eal = (l == 0) ? ea : (const float*)ea_addr;
        const float* Wml = Wm + (size_t)l * (DN + DE) * DN;
        const float* Wel = We + (size_t)l * (2 * DN + DE) * DE;
        cudaMemsetAsync(agg_addr, 0, (size_t)NN * DN * sizeof(float));
        node_mm<<<nsm, 256, NM_SMEM>>>(xl, Wml, 0, (float*)xw_addr);
        msg_mma<<<nsm, 512, MS_SMEM>>>(eal, src, dst, Wml + 128 * DN, bm + l * DN);
        upd_mma<<<nsm, 256, UP_SMEM>>>(xl, Wa + (size_t)l * KA * DN, ba + l * DN);
        node_mm<<<nsm, 256, NM_SMEM>>>((const float*)x_addr, Wel, 1, (float*)xe_addr);
        edge_mma<<<nsm, 512, ED_SMEM>>>(eal, src, dst, Wel + 256 * DE, be + l * DE);
    }
    head_kernel<<<nsm, 256, SM_HED>>>(W1, b1, W2, b2, out);
}

// round 9
// speedup vs baseline: 7.5272x; 1.0454x over previous
#include <cuda_runtime.h>
#include <cstdint>

#define NN 50000
#define NE 500000
#define DN 128
#define DE 64
#define KA 256
#define HM 64

__device__ float g_x[NN * DN];
__device__ float g_ea[NE * DE];
__device__ float g_agg[NN * DN];
__device__ float g_cnt[NN];
__device__ float g_xw[NN * DN];   // x @ Wm[0:128]
__device__ float g_xe[NN * DN];   // x @ [We[0:128] | We[128:256]]

// ===================== helpers =====================
__device__ __forceinline__ uint32_t smem_u32(const void* p) {
    uint32_t a;
    asm("{ .reg .u64 t; cvta.to.shared.u64 t, %1; cvt.u32.u64 %0, t; }" : "=r"(a) : "l"(p));
    return a;
}
#define LDSM4(r0, r1, r2, r3, addr) \
    asm volatile("ldmatrix.sync.aligned.m8n8.x4.shared.b16 {%0,%1,%2,%3}, [%4];" \
                 : "=r"(r0), "=r"(r1), "=r"(r2), "=r"(r3) : "r"(addr))
#define MMA(c, a, b) \
    asm volatile("mma.sync.aligned.m16n8k16.row.col.f32.bf16.bf16.f32 " \
                 "{%0,%1,%2,%3},{%4,%5,%6,%7},{%8,%9},{%0,%1,%2,%3};" \
                 : "+f"((c)[0]), "+f"((c)[1]), "+f"((c)[2]), "+f"((c)[3]) \
                 : "r"((a)[0]), "r"((a)[1]), "r"((a)[2]), "r"((a)[3]), \
                   "r"((b)[0]), "r"((b)[1]))
#define BARG(id) asm volatile("bar.sync %0, %1;" :: "r"(id), "r"(256) : "memory")
#define RED2(p, a, b) \
    asm volatile("red.global.add.v2.f32 [%0], {%1, %2};" :: "l"(p), "f"(a), "f"(b) : "memory")

__device__ __forceinline__ void splitp(float a, float b, uint32_t& hi, uint32_t& lo) {
    uint32_t ua = __float_as_uint(a), ub = __float_as_uint(b);
    hi = __byte_perm(ua, ub, 0x7632);
    float la = a - __uint_as_float(ua & 0xFFFF0000u);
    float lb = b - __uint_as_float(ub & 0xFFFF0000u);
    lo = __byte_perm(__float_as_uint(la), __float_as_uint(lb), 0x7632);
}

// ===================== cnt =====================
__global__ void cnt_kernel(const int* __restrict__ dst) {
    int e = blockIdx.x * blockDim.x + threadIdx.x;
    if (e < NE) atomicAdd(&g_cnt[dst[e]], 1.0f);
}

// ============ NODE BOTH: out_e = x@[We1|We2], out_m = x@Wm1 ============
#define NB_P 272
#define NB_WE_H 0
#define NB_WE_L 34816
#define NB_WM_H 69632
#define NB_WM_L 104448
#define NB_A_H 139264
#define NB_A_L 156672
#define NB_SMEM 174080

__global__ void __launch_bounds__(256, 1)
node_both(const float* __restrict__ xin, const float* __restrict__ We,
          const float* __restrict__ Wm, int do_e, int do_m,
          float* __restrict__ out_e, float* __restrict__ out_m) {
    extern __shared__ char sm[];
    const uint32_t sb = smem_u32(sm);
    const int t = threadIdx.x, lane = t & 31, wid = t >> 5;

    if (do_e) {
        for (int i = t; i < 128 * 64; i += 256) {
            int n = i & 127, kp = i >> 7, k = 2 * kp;
            float w0, w1;
            if (n < 64) { w0 = We[k * 64 + n]; w1 = We[(k + 1) * 64 + n]; }
            else { w0 = We[(128 + k) * 64 + n - 64]; w1 = We[(129 + k) * 64 + n - 64]; }
            uint32_t h, l;
            splitp(w0, w1, h, l);
            *(uint32_t*)(sm + NB_WE_H + n * NB_P + kp * 4) = h;
            *(uint32_t*)(sm + NB_WE_L + n * NB_P + kp * 4) = l;
        }
    }
    if (do_m) {
        for (int i = t; i < 128 * 64; i += 256) {
            int n = i & 127, kp = i >> 7, k = 2 * kp;
            uint32_t h, l;
            splitp(Wm[k * 128 + n], Wm[(k + 1) * 128 + n], h, l);
            *(uint32_t*)(sm + NB_WM_H + n * NB_P + kp * 4) = h;
            *(uint32_t*)(sm + NB_WM_L + n * NB_P + kp * 4) = l;
        }
    }

    const int we = wid >> 1, wo = wid & 1;
    const int am = we * 16 + (lane & 15);
    const int ak = (lane >> 4) << 3;
    const int bn0 = wo * 64 + (lane & 7) + ((lane >> 4) << 3);
    const int bk = (lane & 8) ? 8 : 0;
    const int ntiles = (NN + 63) >> 6;

    for (int tile = blockIdx.x; tile < ntiles; tile += gridDim.x) {
        __syncthreads();
        for (int i = t; i < 64 * 16; i += 256) {
            int row = i >> 4, gg = i & 15, k0 = gg * 8;
            int nd = (tile << 6) + row;
            uint4 H = make_uint4(0, 0, 0, 0), L = H;
            if (nd < NN) {
                float4 v0 = *(const float4*)(xin + (size_t)nd * DN + k0);
                float4 v1 = *(const float4*)(xin + (size_t)nd * DN + k0 + 4);
                splitp(v0.x, v0.y, H.x, L.x); splitp(v0.z, v0.w, H.y, L.y);
                splitp(v1.x, v1.y, H.z, L.z); splitp(v1.z, v1.w, H.w, L.w);
            }
            *(uint4*)(sm + NB_A_H + row * NB_P + gg * 16) = H;
            *(uint4*)(sm + NB_A_L + row * NB_P + gg * 16) = L;
        }
        __syncthreads();

        int r0 = we * 16 + (lane >> 2), r1 = r0 + 8;
        int i0 = (tile << 6) + r0, i1 = (tile << 6) + r1;
#pragma unroll
        for (int pass = 0; pass < 2; ++pass) {
            if (pass == 0 && !do_e) continue;
            if (pass == 1 && !do_m) continue;
            const int WH = pass ? NB_WM_H : NB_WE_H;
            const int WL = pass ? NB_WM_L : NB_WE_L;
            float* outp = pass ? out_m : out_e;
            float c[8][4];
#pragma unroll
            for (int n = 0; n < 8; ++n) { c[n][0] = c[n][1] = c[n][2] = c[n][3] = 0.f; }
#pragma unroll
            for (int ks = 0; ks < 8; ++ks) {
                int k0 = ks * 16;
                uint32_t ah[4], al[4];
                uint32_t aoff = am * NB_P + (k0 + ak) * 2;
                LDSM4(ah[0], ah[1], ah[2], ah[3], sb + NB_A_H + aoff);
                LDSM4(al[0], al[1], al[2], al[3], sb + NB_A_L + aoff);
                uint32_t Bh[8][2], Bl[8][2];
#pragma unroll
                for (int p = 0; p < 4; ++p) {
                    uint32_t boff = (uint32_t)(bn0 + p * 16) * NB_P + (k0 + bk) * 2;
                    LDSM4(Bh[2 * p][0], Bh[2 * p][1], Bh[2 * p + 1][0], Bh[2 * p + 1][1],
                          sb + WH + boff);
                    LDSM4(Bl[2 * p][0], Bl[2 * p][1], Bl[2 * p + 1][0], Bl[2 * p + 1][1],
                          sb + WL + boff);
                }
#pragma unroll
                for (int n = 0; n < 8; ++n) MMA(c[n], ah, Bh[n]);
#pragma unroll
                for (int n = 0; n < 8; ++n) MMA(c[n], ah, Bl[n]);
#pragma unroll
                for (int n = 0; n < 8; ++n) MMA(c[n], al, Bh[n]);
            }
#pragma unroll
            for (int n = 0; n < 8; ++n) {
                int col = wo * 64 + n * 8 + (lane & 3) * 2;
                if (i0 < NN)
                    *(float2*)(outp + (size_t)i0 * DN + col) = make_float2(c[n][0], c[n][1]);
                if (i1 < NN)
                    *(float2*)(outp + (size_t)i1 * DN + col) = make_float2(c[n][2], c[n][3]);
            }
        }
    }
}

// ============ MESSAGE: relu(xw[src] + ea@Wm2 + bm) -> red.v2 agg ============
#define MP 144
#define MS_WT_H 0
#define MS_WT_L 18432
#define MS_GRP 36864
#define MS_G_SZ 52736
#define MS_BIAS 142336
#define MS_SMEM 142848

__global__ void __launch_bounds__(512, 1)
msg_mma(const float* __restrict__ ea,
        const int* __restrict__ src, const int* __restrict__ dst,
        const float* __restrict__ W, const float* __restrict__ bias) {
    extern __shared__ char sm[];
    const uint32_t sb = smem_u32(sm);
    float* bs = (float*)(sm + MS_BIAS);
    const int t = threadIdx.x, lane = t & 31, wid = t >> 5;
    const int g = wid >> 3, w8 = wid & 7, t8 = t & 255;

    for (int i = t; i < 128 * 32; i += 512) {
        int n = i & 127, kp = i >> 7;
        uint32_t h, l;
        splitp(W[(2 * kp) * DN + n], W[(2 * kp + 1) * DN + n], h, l);
        *(uint32_t*)(sm + MS_WT_H + n * MP + kp * 4) = h;
        *(uint32_t*)(sm + MS_WT_L + n * MP + kp * 4) = l;
    }
    if (t < 128) bs[t] = bias[t];
    __syncthreads();

    const int GRP = MS_GRP + g * MS_G_SZ;
    const int AH = GRP, AL = GRP + 9216;
    float* xws = (float*)(sm + GRP + 18432);
    int* ssrc = (int*)(sm + GRP + 52224);
    int* sdst = ssrc + 64;
    const int bar = 1 + g;

    const int we = w8 >> 1, wo = w8 & 1;
    const int am = we * 16 + (lane & 15);
    const int ak = (lane >> 4) << 3;
    const int bn0 = wo * 64 + (lane & 7) + ((lane >> 4) << 3);
    const int bk = (lane & 8) ? 8 : 0;
    const int ntiles = (NE + 63) >> 6;

    for (int tile = blockIdx.x * 2 + g; tile < ntiles; tile += gridDim.x * 2) {
        BARG(bar);
        if (t8 < 64) {
            int e = tile * 64 + t8;
            ssrc[t8] = (e < NE) ? src[e] : -1;
            sdst[t8] = (e < NE) ? dst[e] : -1;
        }
        for (int i = t8; i < 64 * 8; i += 256) {
            int row = i >> 3, gg = i & 7, k0 = gg * 8;
            int e = tile * 64 + row;
            uint4 H = make_uint4(0, 0, 0, 0), L = H;
            if (e < NE) {
                float4 v0 = *(const float4*)(ea + (size_t)e * DE + k0);
                float4 v1 = *(const float4*)(ea + (size_t)e * DE + k0 + 4);
                splitp(v0.x, v0.y, H.x, L.x); splitp(v0.z, v0.w, H.y, L.y);
                splitp(v1.x, v1.y, H.z, L.z); splitp(v1.z, v1.w, H.w, L.w);
            }
            *(uint4*)(sm + AH + row * MP + gg * 16) = H;
            *(uint4*)(sm + AL + row * MP + gg * 16) = L;
        }
        BARG(bar);
        for (int i = t8; i < 64 * 32; i += 256) {
            int row = i >> 5, q = i & 31;
            int s = ssrc[row];
            if (s >= 0)
                *(float4*)(xws + row * 132 + q * 4) =
                    *(const float4*)(g_xw + (size_t)s * DN + q * 4);
        }
        BARG(bar);

        float c[8][4];
#pragma unroll
        for (int n = 0; n < 8; ++n) { c[n][0] = c[n][1] = c[n][2] = c[n][3] = 0.f; }
#pragma unroll
        for (int ks = 0; ks < 4; ++ks) {
            int k0 = ks * 16;
            uint32_t ah[4], al[4];
            uint32_t aoff = am * MP + (k0 + ak) * 2;
            LDSM4(ah[0], ah[1], ah[2], ah[3], sb + AH + aoff);
            LDSM4(al[0], al[1], al[2], al[3], sb + AL + aoff);
            uint32_t Bh[8][2], Bl[8][2];
#pragma unroll
            for (int p = 0; p < 4; ++p) {
                uint32_t boff = (uint32_t)(bn0 + p * 16) * MP + (k0 + bk) * 2;
                LDSM4(Bh[2 * p][0], Bh[2 * p][1], Bh[2 * p + 1][0], Bh[2 * p + 1][1],
                      sb + MS_WT_H + boff);
                LDSM4(Bl[2 * p][0], Bl[2 * p][1], Bl[2 * p + 1][0], Bl[2 * p + 1][1],
                      sb + MS_WT_L + boff);
            }
#pragma unroll
            for (int n = 0; n < 8; ++n) MMA(c[n], ah, Bh[n]);
#pragma unroll
            for (int n = 0; n < 8; ++n) MMA(c[n], ah, Bl[n]);
#pragma unroll
            for (int n = 0; n < 8; ++n) MMA(c[n], al, Bh[n]);
        }
        int r0 = we * 16 + (lane >> 2), r1 = r0 + 8;
        int d0 = sdst[r0], d1 = sdst[r1];
#pragma unroll
        for (int n = 0; n < 8; ++n) {
            int col = wo * 64 + n * 8 + (lane & 3) * 2;
            float b0 = bs[col], b1 = bs[col + 1];
            if (d0 >= 0) {
                float v0 = fmaxf(c[n][0] + xws[r0 * 132 + col] + b0, 0.f);
                float v1 = fmaxf(c[n][1] + xws[r0 * 132 + col + 1] + b1, 0.f);
                if (v0 > 0.f || v1 > 0.f)
                    RED2(g_agg + (size_t)d0 * DN + col, v0, v1);
            }
            if (d1 >= 0) {
                float v0 = fmaxf(c[n][2] + xws[r1 * 132 + col] + b0, 0.f);
                float v1 = fmaxf(c[n][3] + xws[r1 * 132 + col + 1] + b1, 0.f);
                if (v0 > 0.f || v1 > 0.f)
                    RED2(g_agg + (size_t)d1 * DN + col, v0, v1);
            }
        }
    }
}

// ============ EDGE: relu(xe1[src] + xe2[dst] + ea@We3 + be) ============
#define EP 144
#define ED_WT_H 0
#define ED_WT_L 9216
#define ED_GRP 18432
#define ED_G_SZ 53760
#define ED_BIAS 125952
#define ED_SMEM 126464

__global__ void __launch_bounds__(512, 1)
edge_mma(const float* __restrict__ ea,
         const int* __restrict__ src, const int* __restrict__ dst,
         const float* __restrict__ W, const float* __restrict__ bias) {
    extern __shared__ char sm[];
    const uint32_t sb = smem_u32(sm);
    float* bs = (float*)(sm + ED_BIAS);
    const int t = threadIdx.x, lane = t & 31, wid = t >> 5;
    const int g = wid >> 3, w8 = wid & 7, t8 = t & 255;

    for (int i = t; i < 64 * 32; i += 512) {
        int n = i & 63, kp = i >> 6;
        uint32_t h, l;
        splitp(W[(2 * kp) * DE + n], W[(2 * kp + 1) * DE + n], h, l);
        *(uint32_t*)(sm + ED_WT_H + n * EP + kp * 4) = h;
        *(uint32_t*)(sm + ED_WT_L + n * EP + kp * 4) = l;
    }
    if (t < 64) bs[t] = bias[t];
    __syncthreads();

    const int GRP = ED_GRP + g * ED_G_SZ;
    const int AH = GRP, AL = GRP + 9216;
    float* xe1s = (float*)(sm + GRP + 18432);
    float* xe2s = (float*)(sm + GRP + 35840);
    int* ssrc = (int*)(sm + GRP + 53248);
    int* sdst = ssrc + 64;
    const int bar = 1 + g;

    const int we = w8 >> 1, wo = w8 & 1;
    const int am = we * 16 + (lane & 15);
    const int ak = (lane >> 4) << 3;
    const int bn0 = wo * 32 + (lane & 7) + ((lane >> 4) << 3);
    const int bk = (lane & 8) ? 8 : 0;
    const int ntiles = (NE + 63) >> 6;

    for (int tile = blockIdx.x * 2 + g; tile < ntiles; tile += gridDim.x * 2) {
        BARG(bar);
        if (t8 < 64) {
            int e = tile * 64 + t8;
            ssrc[t8] = (e < NE) ? src[e] : -1;
            sdst[t8] = (e < NE) ? dst[e] : -1;
        }
        for (int i = t8; i < 64 * 8; i += 256) {
            int row = i >> 3, gg = i & 7, k0 = gg * 8;
            int e = tile * 64 + row;
            uint4 H = make_uint4(0, 0, 0, 0), L = H;
            if (e < NE) {
                float4 v0 = *(const float4*)(ea + (size_t)e * DE + k0);
                float4 v1 = *(const float4*)(ea + (size_t)e * DE + k0 + 4);
                splitp(v0.x, v0.y, H.x, L.x); splitp(v0.z, v0.w, H.y, L.y);
                splitp(v1.x, v1.y, H.z, L.z); splitp(v1.z, v1.w, H.w, L.w);
            }
            *(uint4*)(sm + AH + row * EP + gg * 16) = H;
            *(uint4*)(sm + AL + row * EP + gg * 16) = L;
        }
        BARG(bar);
        for (int i = t8; i < 64 * 16; i += 256) {
            int row = i >> 4, q = i & 15;
            int s = ssrc[row], d = sdst[row];
            if (s >= 0) {
                *(float4*)(xe1s + row * 68 + q * 4) =
                    *(const float4*)(g_xe + (size_t)s * DN + q * 4);
                *(float4*)(xe2s + row * 68 + q * 4) =
                    *(const float4*)(g_xe + (size_t)d * DN + 64 + q * 4);
            }
        }
        BARG(bar);

        float c[4][4];
#pragma unroll
        for (int n = 0; n < 4; ++n) { c[n][0] = c[n][1] = c[n][2] = c[n][3] = 0.f; }
#pragma unroll
        for (int ks = 0; ks < 4; ++ks) {
            int k0 = ks * 16;
            uint32_t ah[4], al[4];
            uint32_t aoff = am * EP + (k0 + ak) * 2;
            LDSM4(ah[0], ah[1], ah[2], ah[3], sb + AH + aoff);
            LDSM4(al[0], al[1], al[2], al[3], sb + AL + aoff);
            uint32_t Bh[4][2], Bl[4][2];
#pragma unroll
            for (int p = 0; p < 2; ++p) {
                uint32_t boff = (uint32_t)(bn0 + p * 16) * EP + (k0 + bk) * 2;
                LDSM4(Bh[2 * p][0], Bh[2 * p][1], Bh[2 * p + 1][0], Bh[2 * p + 1][1],
                      sb + ED_WT_H + boff);
                LDSM4(Bl[2 * p][0], Bl[2 * p][1], Bl[2 * p + 1][0], Bl[2 * p + 1][1],
                      sb + ED_WT_L + boff);
            }
#pragma unroll
            for (int n = 0; n < 4; ++n) MMA(c[n], ah, Bh[n]);
#pragma unroll
            for (int n = 0; n < 4; ++n) MMA(c[n], ah, Bl[n]);
#pragma unroll
            for (int n = 0; n < 4; ++n) MMA(c[n], al, Bh[n]);
        }
        int r0 = we * 16 + (lane >> 2), r1 = r0 + 8;
        int e0 = tile * 64 + r0, e1 = tile * 64 + r1;
#pragma unroll
        for (int n = 0; n < 4; ++n) {
            int col = wo * 32 + n * 8 + (lane & 3) * 2;
            float b0 = bs[col], b1 = bs[col + 1];
            if (e0 < NE) {
                float2 v = make_float2(
                    fmaxf(c[n][0] + xe1s[r0 * 68 + col] + xe2s[r0 * 68 + col] + b0, 0.f),
                    fmaxf(c[n][1] + xe1s[r0 * 68 + col + 1] + xe2s[r0 * 68 + col + 1] + b1, 0.f));
                *(float2*)(g_ea + (size_t)e0 * DE + col) = v;
            }
            if (e1 < NE) {
                float2 v = make_float2(
                    fmaxf(c[n][2] + xe1s[r1 * 68 + col] + xe2s[r1 * 68 + col] + b0, 0.f),
                    fmaxf(c[n][3] + xe1s[r1 * 68 + col + 1] + xe2s[r1 * 68 + col + 1] + b1, 0.f));
                *(float2*)(g_ea + (size_t)e1 * DE + col) = v;
            }
        }
    }
}

// ============ UPDATE (mma, software-pipelined) ============
#define UP_P 528
#define UP_WT_H 0
#define UP_WT_L 67584
#define UP_A_H 135168
#define UP_A_L 168960
#define UP_BIAS 202752
#define UP_SSQ 203264
#define UP_SMEM 203776

#define UP_STAGE(tt) do { \
    for (int i = t; i < 64 * 32; i += 256) { \
        int row = i >> 5, gg = i & 31, k0 = gg * 8; \
        int nd = ((tt) << 6) + row; \
        uint4 H = make_uint4(0, 0, 0, 0), L = H; \
        if (nd < NN) { \
            float4 v0, v1; \
            if (k0 < DN) { \
                float iv = 1.f / fmaxf(g_cnt[nd], 1.f); \
                v0 = *(const float4*)(g_agg + (size_t)nd * DN + k0); \
                v1 = *(const float4*)(g_agg + (size_t)nd * DN + k0 + 4); \
                v0.x *= iv; v0.y *= iv; v0.z *= iv; v0.w *= iv; \
                v1.x *= iv; v1.y *= iv; v1.z *= iv; v1.w *= iv; \
            } else { \
                v0 = *(const float4*)(xin + (size_t)nd * DN + (k0 - DN)); \
                v1 = *(const float4*)(xin + (size_t)nd * DN + (k0 - DN) + 4); \
            } \
            splitp(v0.x, v0.y, H.x, L.x); splitp(v0.z, v0.w, H.y, L.y); \
            splitp(v1.x, v1.y, H.z, L.z); splitp(v1.z, v1.w, H.w, L.w); \
        } \
        *(uint4*)(sm + UP_A_H + row * UP_P + gg * 16) = H; \
        *(uint4*)(sm + UP_A_L + row * UP_P + gg * 16) = L; \
    } \
} while (0)

__global__ void __launch_bounds__(256, 1)
upd_mma(const float* __restrict__ xin,
        const float* __restrict__ W, const float* __restrict__ bias) {
    extern __shared__ char sm[];
    const uint32_t sb = smem_u32(sm);
    float* bs = (float*)(sm + UP_BIAS);
    float* ssq = (float*)(sm + UP_SSQ);
    const int t = threadIdx.x, lane = t & 31, wid = t >> 5;

    for (int i = t; i < 128 * 128; i += 256) {
        int n = i & 127, kp = i >> 7;
        uint32_t h, l;
        splitp(W[(2 * kp) * DN + n], W[(2 * kp + 1) * DN + n], h, l);
        *(uint32_t*)(sm + UP_WT_H + n * UP_P + kp * 4) = h;
        *(uint32_t*)(sm + UP_WT_L + n * UP_P + kp * 4) = l;
    }
    if (t < 128) bs[t] = bias[t];

    const int we = wid >> 1, wo = wid & 1;
    const int am = we * 16 + (lane & 15);
    const int ak = (lane >> 4) << 3;
    const int bn0 = wo * 64 + (lane & 7) + ((lane >> 4) << 3);
    const int bk = (lane & 8) ? 8 : 0;
    const int ntiles = (NN + 63) >> 6;

    int tile = blockIdx.x;
    if (tile < ntiles) UP_STAGE(tile);

    for (; tile < ntiles; tile += gridDim.x) {
        __syncthreads();   // A + weights ready
        float c[8][4];
#pragma unroll
        for (int n = 0; n < 8; ++n) { c[n][0] = c[n][1] = c[n][2] = c[n][3] = 0.f; }
#pragma unroll
        for (int ks = 0; ks < 16; ++ks) {
            int k0 = ks * 16;
            uint32_t ah[4], al[4];
            uint32_t aoff = am * UP_P + (k0 + ak) * 2;
            LDSM4(ah[0], ah[1], ah[2], ah[3], sb + UP_A_H + aoff);
            LDSM4(al[0], al[1], al[2], al[3], sb + UP_A_L + aoff);
            uint32_t Bh[8][2], Bl[8][2];
#pragma unroll
            for (int p = 0; p < 4; ++p) {
                uint32_t boff = (uint32_t)(bn0 + p * 16) * UP_P + (k0 + bk) * 2;
                LDSM4(Bh[2 * p][0], Bh[2 * p][1], Bh[2 * p + 1][0], Bh[2 * p + 1][1],
                      sb + UP_WT_H + boff);
                LDSM4(Bl[2 * p][0], Bl[2 * p][1], Bl[2 * p + 1][0], Bl[2 * p + 1][1],
                      sb + UP_WT_L + boff);
            }
#pragma unroll
            for (int n = 0; n < 8; ++n) MMA(c[n], ah, Bh[n]);
#pragma unroll
            for (int n = 0; n < 8; ++n) MMA(c[n], ah, Bl[n]);
#pragma unroll
            for (int n = 0; n < 8; ++n) MMA(c[n], al, Bh[n]);
        }
        __syncthreads();   // all warps done reading A
        int nt = tile + gridDim.x;
        if (nt < ntiles) UP_STAGE(nt);   // overlap next staging with epilogue

        int r0 = we * 16 + (lane >> 2), r1 = r0 + 8;
        float s0 = 0.f, s1 = 0.f;
#pragma unroll
        for (int n = 0; n < 8; ++n) {
            int col = wo * 64 + n * 8 + (lane & 3) * 2;
            float b0 = bs[col], b1 = bs[col + 1];
            c[n][0] = fmaxf(c[n][0] + b0, 0.f);
            c[n][1] = fmaxf(c[n][1] + b1, 0.f);
            c[n][2] = fmaxf(c[n][2] + b0, 0.f);
            c[n][3] = fmaxf(c[n][3] + b1, 0.f);
            s0 += c[n][0] * c[n][0] + c[n][1] * c[n][1];
            s1 += c[n][2] * c[n][2] + c[n][3] * c[n][3];
        }
        s0 += __shfl_xor_sync(0xffffffffu, s0, 1);
        s0 += __shfl_xor_sync(0xffffffffu, s0, 2);
        s1 += __shfl_xor_sync(0xffffffffu, s1, 1);
        s1 += __shfl_xor_sync(0xffffffffu, s1, 2);
        if ((lane & 3) == 0) {
            ssq[wo * 64 + r0] = s0;
            ssq[wo * 64 + r1] = s1;
        }
        __syncthreads();   // ssq ready (and A-next writes ordered)
        float sc0 = 1.f / fmaxf(sqrtf(ssq[r0] + ssq[64 + r0]), 1e-12f);
        float sc1 = 1.f / fmaxf(sqrtf(ssq[r1] + ssq[64 + r1]), 1e-12f);
        int i0 = (tile << 6) + r0, i1 = (tile << 6) + r1;
#pragma unroll
        for (int n = 0; n < 8; ++n) {
            int col = wo * 64 + n * 8 + (lane & 3) * 2;
            if (i0 < NN)
                *(float2*)(g_x + (size_t)i0 * DN + col) =
                    make_float2(c[n][0] * sc0, c[n][1] * sc0);
            if (i1 < NN)
                *(float2*)(g_x + (size_t)i1 * DN + col) =
                    make_float2(c[n][2] * sc1, c[n][3] * sc1);
        }
    }
}

// ===================== HEAD (SIMT) =====================
__global__ void __launch_bounds__(256, 1)
head_kernel(const float* __restrict__ W1, const float* __restrict__ b1,
            const float* __restrict__ W2, const float* __restrict__ b2,
            float* __restrict__ out) {
    extern __shared__ float smf[];
    float* W1s = smf;
    float* b1s = W1s + DN * HM;
    float* W2s = b1s + HM;
    float* b2s = W2s + HM * DN;
    float* ins = b2s + DN;
    float* hs = ins + 32 * DN;
    const int t = threadIdx.x;
    for (int i = t; i < DN * HM; i += 256) W1s[i] = W1[i];
    for (int i = t; i < HM * DN; i += 256) W2s[i] = W2[i];
    if (t < HM) b1s[t] = b1[t];
    if (t < DN) b2s[t] = b2[t];
    const int tx1 = t & 15, ty1 = t >> 4;
    const int tx2 = t & 31, ty2 = t >> 5;
    const int ntiles = (NN + 31) >> 5;
    for (int tile = blockIdx.x; tile < ntiles; tile += gridDim.x) {
        __syncthreads();
        for (int idx = t; idx < 32 * DN; idx += 256) {
            int it = idx >> 7, c = idx & 127;
            int i = (tile << 5) + it;
            ins[idx] = (i < NN) ? g_x[(size_t)i * DN + c] : 0.f;
        }
        __syncthreads();
        {
            float acc[2][4] = {{0, 0, 0, 0}, {0, 0, 0, 0}};
            const float* inp = ins + (ty1 * 2) * DN;
#pragma unroll 2
            for (int k = 0; k < DN; ++k) {
                float4 w = *(const float4*)(W1s + k * HM + 4 * tx1);
                float v0 = inp[k], v1 = inp[DN + k];
                acc[0][0] += v0 * w.x; acc[0][1] += v0 * w.y;
                acc[0][2] += v0 * w.z; acc[0][3] += v0 * w.w;
                acc[1][0] += v1 * w.x; acc[1][1] += v1 * w.y;
                acc[1][2] += v1 * w.z; acc[1][3] += v1 * w.w;
            }
#pragma unroll
            for (int jj = 0; jj < 2; ++jj) {
                int it = ty1 * 2 + jj;
#pragma unroll
                for (int c = 0; c < 4; ++c)
                    hs[it * HM + 4 * tx1 + c] = fmaxf(acc[jj][c] + b1s[4 * tx1 + c], 0.f);
            }
        }
        __syncthreads();
        {
            float acc[4][4];
#pragma unroll
            for (int ii = 0; ii < 4; ++ii)
#pragma unroll
                for (int c = 0; c < 4; ++c) acc[ii][c] = 0.f;
            const float* inp = hs + (ty2 * 4) * HM;
#pragma unroll 2
            for (int k = 0; k < HM; ++k) {
                float4 w = *(const float4*)(W2s + k * DN + 4 * tx2);
#pragma unroll
                for (int ii = 0; ii < 4; ++ii) {
                    float v = inp[ii * HM + k];
                    acc[ii][0] += v * w.x; acc[ii][1] += v * w.y;
                    acc[ii][2] += v * w.z; acc[ii][3] += v * w.w;
                }
            }
#pragma unroll
            for (int ii = 0; ii < 4; ++ii) {
                int i = (tile << 5) + ty2 * 4 + ii;
                if (i < NN) {
                    float* o = out + (size_t)i * DN + 4 * tx2;
#pragma unroll
                    for (int c = 0; c < 4; ++c) o[c] = acc[ii][c] + b2s[4 * tx2 + c];
                }
            }
        }
    }
}

// ===================== launch =====================
extern "C" void kernel_launch(void* const* d_in, const int* in_sizes, int n_in,
                              void* d_out, int out_size) {
    (void)in_sizes; (void)n_in; (void)out_size;
    const float* x  = (const float*)d_in[0];
    const float* ea = (const float*)d_in[1];
    const int*   ei = (const int*)d_in[2];
    const float* Wm = (const float*)d_in[3];
    const float* bm = (const float*)d_in[4];
    const float* Wa = (const float*)d_in[5];
    const float* ba = (const float*)d_in[6];
    const float* We = (const float*)d_in[7];
    const float* be = (const float*)d_in[8];
    const float* W1 = (const float*)d_in[9];
    const float* b1 = (const float*)d_in[10];
    const float* W2 = (const float*)d_in[11];
    const float* b2 = (const float*)d_in[12];
    float* out = (float*)d_out;
    const int* src = ei;
    const int* dst = ei + NE;

    int nsm = 0;
    cudaDeviceGetAttribute(&nsm, cudaDevAttrMultiProcessorCount, 0);
    if (nsm <= 0) nsm = 148;

    const int SM_HED = (DN * HM + HM + HM * DN + DN + 32 * DN + 32 * HM) * 4;

    cudaFuncSetAttribute(node_both, cudaFuncAttributeMaxDynamicSharedMemorySize, NB_SMEM);
    cudaFuncSetAttribute(msg_mma,  cudaFuncAttributeMaxDynamicSharedMemorySize, MS_SMEM);
    cudaFuncSetAttribute(edge_mma, cudaFuncAttributeMaxDynamicSharedMemorySize, ED_SMEM);
    cudaFuncSetAttribute(upd_mma,  cudaFuncAttributeMaxDynamicSharedMemorySize, UP_SMEM);
    cudaFuncSetAttribute(head_kernel, cudaFuncAttributeMaxDynamicSharedMemorySize, SM_HED);

    void *agg_addr = 0, *cnt_addr = 0, *x_addr = 0, *ea_addr = 0;
    void *xw_addr = 0, *xe_addr = 0;
    cudaGetSymbolAddress(&agg_addr, g_agg);
    cudaGetSymbolAddress(&cnt_addr, g_cnt);
    cudaGetSymbolAddress(&x_addr, g_x);
    cudaGetSymbolAddress(&ea_addr, g_ea);
    cudaGetSymbolAddress(&xw_addr, g_xw);
    cudaGetSymbolAddress(&xe_addr, g_xe);

    cudaMemsetAsync(cnt_addr, 0, NN * sizeof(float));
    cnt_kernel<<<(NE + 255) / 256, 256>>>(dst);

    // layer-0 pre: xw = x @ Wm1(0)
    node_both<<<nsm, 256, NB_SMEM>>>(x, We, Wm, 0, 1,
                                     (float*)xe_addr, (float*)xw_addr);

    for (int l = 0; l < 3; ++l) {
        const float* xl  = (l == 0) ? x  : (const float*)x_addr;
        const float* eal = (l == 0) ? ea : (const float*)ea_addr;
        const float* Wml = Wm + (size_t)l * (DN + DE) * DN;
        const float* Wel = We + (size_t)l * (2 * DN + DE) * DE;
        const float* Wmn = (l < 2) ? Wm + (size_t)(l + 1) * (DN + DE) * DN : Wm;
        cudaMemsetAsync(agg_addr, 0, (size_t)NN * DN * sizeof(float));
        msg_mma<<<nsm, 512, MS_SMEM>>>(eal, src, dst, Wml + 128 * DN, bm + l * DN);
        upd_mma<<<nsm, 256, UP_SMEM>>>(xl, Wa + (size_t)l * KA * DN, ba + l * DN);
        node_both<<<nsm, 256, NB_SMEM>>>((const float*)x_addr, Wel, Wmn,
                                         1, (l < 2) ? 1 : 0,
                                         (float*)xe_addr, (float*)xw_addr);
        edge_mma<<<nsm, 512, ED_SMEM>>>(eal, src, dst, Wel + 256 * DE, be + l * DE);
    }
    head_kernel<<<nsm, 256, SM_HED>>>(W1, b1, W2, b2, out);
}